// round 1
// baseline (speedup 1.0000x reference)
#include <cuda_runtime.h>
#include <cuda_bf16.h>

#define NN 50000
#define EE 1600000
#define DD 128
#define NB 196            // ceil(NN/256)

// ---------------- scratch (device globals; no allocation allowed) ----------
__device__ float g_x[NN * 128];      // node features
__device__ float g_y[NN * 256];      // [Y0 | Y1] per node (row stride 256)
__device__ float g_root[NN * 128];   // X @ root_w
__device__ float g_h[NN * 128];      // MLP hidden
__device__ int   g_cnt[2 * NN];      // per-relation in-degree
__device__ int   g_off[NN + 1];      // CSR offsets by dst
__device__ int   g_cur[NN];          // scatter cursors
__device__ int   g_list[EE];         // packed (src<<1)|rel, grouped by dst
__device__ float g_inv[2 * NN];      // 1/max(cnt_r,1)
__device__ int   g_loc[NN];          // block-local inclusive scan
__device__ int   g_bsum[256];
__device__ int   g_bpre[256];

__device__ __forceinline__ float lrelu(float v) { return v > 0.f ? v : 0.01f * v; }

// ---------------- edge preprocessing ----------------------------------------
__global__ void k_zero_cnt() {
    int i = blockIdx.x * 256 + threadIdx.x;
    if (i < 2 * NN) g_cnt[i] = 0;
}

__global__ void k_hist(const int* __restrict__ ei, const int* __restrict__ et) {
    int e = blockIdx.x * 256 + threadIdx.x;
    if (e < EE) {
        int dst = ei[EE + e];
        int r   = et[e];
        atomicAdd(&g_cnt[r * NN + dst], 1);
    }
}

__global__ void k_scan1() {
    __shared__ int s[256];
    int t = threadIdx.x;
    int i = blockIdx.x * 256 + t;
    int d = 0;
    if (i < NN) d = g_cnt[i] + g_cnt[NN + i];
    s[t] = d;
    __syncthreads();
    #pragma unroll
    for (int off = 1; off < 256; off <<= 1) {
        int v = (t >= off) ? s[t - off] : 0;
        __syncthreads();
        s[t] += v;
        __syncthreads();
    }
    if (i < NN) g_loc[i] = s[t];
    if (t == 255) g_bsum[blockIdx.x] = s[255];
}

__global__ void k_scan2() {
    __shared__ int s[256];
    int t = threadIdx.x;
    int d = (t < NB) ? g_bsum[t] : 0;
    s[t] = d;
    __syncthreads();
    #pragma unroll
    for (int off = 1; off < 256; off <<= 1) {
        int v = (t >= off) ? s[t - off] : 0;
        __syncthreads();
        s[t] += v;
        __syncthreads();
    }
    g_bpre[t] = s[t] - d;   // exclusive
}

__global__ void k_scan3() {
    int i = blockIdx.x * 256 + threadIdx.x;
    if (i >= NN) return;
    int c0 = g_cnt[i], c1 = g_cnt[NN + i];
    int deg = c0 + c1;
    int excl = g_bpre[blockIdx.x] + g_loc[i] - deg;
    g_off[i] = excl;
    g_cur[i] = excl;
    g_inv[i]      = 1.0f / (c0 > 0 ? (float)c0 : 1.0f);
    g_inv[NN + i] = 1.0f / (c1 > 0 ? (float)c1 : 1.0f);
    if (i == NN - 1) g_off[NN] = excl + deg;
}

__global__ void k_fill(const int* __restrict__ ei, const int* __restrict__ et) {
    int e = blockIdx.x * 256 + threadIdx.x;
    if (e < EE) {
        int src = ei[e];
        int dst = ei[EE + e];
        int r   = et[e];
        int pos = atomicAdd(&g_cur[dst], 1);
        g_list[pos] = (src << 1) | r;
    }
}

// ---------------- SIMT fp32 GEMM: C[M,128] (+)= act(A[M,K] @ B[K,128] + bias)
// BM=128 BN=128 BK=8, 256 threads, TM=TN=8
template <int ACT, bool ACCUM>
__global__ void k_gemm128(const float* __restrict__ A, const float* __restrict__ B,
                          const float* __restrict__ bias, float* __restrict__ C,
                          int M, int K, int ldc) {
    __shared__ float As[8][128];
    __shared__ float Bs[8][128];

    int tid = threadIdx.x;
    int tx = tid & 15;          // 0..15 -> 8 cols each
    int ty = tid >> 4;          // 0..15 -> 8 rows each
    int m0 = blockIdx.x * 128;

    float acc[8][8];
    #pragma unroll
    for (int i = 0; i < 8; i++)
        #pragma unroll
        for (int j = 0; j < 8; j++) acc[i][j] = 0.f;

    int am = tid >> 1;                   // row within tile for A loads
    int ak0 = (tid & 1) * 4;             // starting k within BK

    for (int k0 = 0; k0 < K; k0 += 8) {
        // load A tile (128 x 8)
        {
            int row = m0 + am;
            #pragma unroll
            for (int u = 0; u < 4; u++) {
                int kk = ak0 + u;
                float v = 0.f;
                if (row < M && (k0 + kk) < K) v = A[(long)row * K + k0 + kk];
                As[kk][am] = v;
            }
        }
        // load B tile (8 x 128)
        {
            int kk = tid >> 5;
            int n  = (tid & 31) * 4;
            #pragma unroll
            for (int u = 0; u < 4; u++) {
                float v = 0.f;
                if ((k0 + kk) < K) v = B[(long)(k0 + kk) * 128 + n + u];
                Bs[kk][n + u] = v;
            }
        }
        __syncthreads();

        #pragma unroll
        for (int kk = 0; kk < 8; kk++) {
            float a[8], b[8];
            #pragma unroll
            for (int i = 0; i < 8; i++) a[i] = As[kk][ty * 8 + i];
            #pragma unroll
            for (int j = 0; j < 8; j++) b[j] = Bs[kk][tx * 8 + j];
            #pragma unroll
            for (int i = 0; i < 8; i++)
                #pragma unroll
                for (int j = 0; j < 8; j++)
                    acc[i][j] = fmaf(a[i], b[j], acc[i][j]);
        }
        __syncthreads();
    }

    #pragma unroll
    for (int i = 0; i < 8; i++) {
        int row = m0 + ty * 8 + i;
        if (row >= M) continue;
        #pragma unroll
        for (int j = 0; j < 8; j++) {
            int col = tx * 8 + j;
            float v = acc[i][j];
            if (bias) v += bias[col];
            if (ACT == 1) v = lrelu(v);
            else if (ACT == 2) v = fmaxf(v, 0.f);
            long idx = (long)row * ldc + col;
            if (ACCUM) C[idx] += v;
            else       C[idx] = v;
        }
    }
}

// ---------------- RGCN gather/combine: one warp per destination node --------
__global__ void k_gather(const float* __restrict__ y, const float* __restrict__ root,
                         const float* __restrict__ bias, float* __restrict__ xout) {
    int gw = (blockIdx.x * blockDim.x + threadIdx.x) >> 5;
    int lane = threadIdx.x & 31;
    if (gw >= NN) return;

    int beg = g_off[gw], end = g_off[gw + 1];
    float4 a0 = make_float4(0.f, 0.f, 0.f, 0.f);
    float4 a1 = make_float4(0.f, 0.f, 0.f, 0.f);

    for (int j = beg; j < end; j++) {
        int p = __ldg(&g_list[j]);                 // uniform across warp
        const float4 v = *(const float4*)(y + (long)(p >> 1) * 256 + (p & 1) * 128 + lane * 4);
        if (p & 1) { a1.x += v.x; a1.y += v.y; a1.z += v.z; a1.w += v.w; }
        else       { a0.x += v.x; a0.y += v.y; a0.z += v.z; a0.w += v.w; }
    }

    float i0 = g_inv[gw], i1 = g_inv[NN + gw];
    long base = (long)gw * 128 + lane * 4;
    float4 rt = *(const float4*)(root + base);
    float b0 = bias[lane * 4 + 0], b1 = bias[lane * 4 + 1];
    float b2 = bias[lane * 4 + 2], b3 = bias[lane * 4 + 3];

    float4 o;
    o.x = lrelu(rt.x + b0 + a0.x * i0 + a1.x * i1);
    o.y = lrelu(rt.y + b1 + a0.y * i0 + a1.y * i1);
    o.z = lrelu(rt.z + b2 + a0.z * i0 + a1.z * i1);
    o.w = lrelu(rt.w + b3 + a0.w * i0 + a1.w * i1);
    *(float4*)(xout + base) = o;
}

// ---------------- MLP head (D=128 -> 2): one warp per node -------------------
__global__ void k_mlp2(const float* __restrict__ h, const float* __restrict__ w2,
                       const float* __restrict__ b2, float* __restrict__ out) {
    int gw = (blockIdx.x * blockDim.x + threadIdx.x) >> 5;
    int lane = threadIdx.x & 31;
    if (gw >= NN) return;
    float a0 = 0.f, a1 = 0.f;
    #pragma unroll
    for (int kk = 0; kk < 4; kk++) {
        int k = lane + kk * 32;
        float hv = h[(long)gw * 128 + k];
        a0 = fmaf(hv, w2[2 * k + 0], a0);
        a1 = fmaf(hv, w2[2 * k + 1], a1);
    }
    #pragma unroll
    for (int off = 16; off > 0; off >>= 1) {
        a0 += __shfl_down_sync(0xFFFFFFFFu, a0, off);
        a1 += __shfl_down_sync(0xFFFFFFFFu, a1, off);
    }
    if (lane == 0) {
        out[2 * gw + 0] = a0 + b2[0];
        out[2 * gw + 1] = a1 + b2[1];
    }
}

// ---------------- launch -----------------------------------------------------
extern "C" void kernel_launch(void* const* d_in, const int* in_sizes, int n_in,
                              void* d_out, int out_size) {
    const float* des     = (const float*)d_in[0];
    const float* tweets  = (const float*)d_in[1];
    const float* numf    = (const float*)d_in[2];
    const float* catf    = (const float*)d_in[3];
    const int*   ei      = (const int*)d_in[4];
    const int*   et      = (const int*)d_in[5];
    const float* des_w   = (const float*)d_in[6];
    const float* des_b   = (const float*)d_in[7];
    const float* tweet_w = (const float*)d_in[8];
    const float* tweet_b = (const float*)d_in[9];
    const float* num_w   = (const float*)d_in[10];
    const float* num_b   = (const float*)d_in[11];
    const float* cat_w   = (const float*)d_in[12];
    const float* cat_b   = (const float*)d_in[13];
    const float* rel_w   = (const float*)d_in[14];   // [2][2][128][128]
    const float* root_w  = (const float*)d_in[15];   // [2][128][128]
    const float* rgcn_b  = (const float*)d_in[16];   // [2][128]
    const float* mlp_w1  = (const float*)d_in[17];
    const float* mlp_b1  = (const float*)d_in[18];
    const float* mlp_w2  = (const float*)d_in[19];   // [128][2]
    const float* mlp_b2  = (const float*)d_in[20];
    float* out = (float*)d_out;

    float *px, *py, *proot, *ph;
    cudaGetSymbolAddress((void**)&px,    g_x);
    cudaGetSymbolAddress((void**)&py,    g_y);
    cudaGetSymbolAddress((void**)&proot, g_root);
    cudaGetSymbolAddress((void**)&ph,    g_h);

    // ---- CSR build (edge structure fixed, rebuilt every call for determinism)
    k_zero_cnt<<<(2 * NN + 255) / 256, 256>>>();
    k_hist<<<EE / 256, 256>>>(ei, et);
    k_scan1<<<NB, 256>>>();
    k_scan2<<<1, 256>>>();
    k_scan3<<<NB, 256>>>();
    k_fill<<<EE / 256, 256>>>(ei, et);

    int gm = (NN + 127) / 128;

    // ---- multimodal projections: x = sum of 4 lrelu(linear)
    k_gemm128<1, false><<<gm, 256>>>(des,    des_w,   des_b,   px, NN, 768, 128);
    k_gemm128<1, true ><<<gm, 256>>>(tweets, tweet_w, tweet_b, px, NN, 768, 128);
    k_gemm128<1, true ><<<gm, 256>>>(numf,   num_w,   num_b,   px, NN, 5,   128);
    k_gemm128<1, true ><<<gm, 256>>>(catf,   cat_w,   cat_b,   px, NN, 6,   128);

    // ---- 2 RGCN layers
    for (int l = 0; l < 2; l++) {
        const float* w0 = rel_w + (long)(l * 2 + 0) * 128 * 128;
        const float* w1 = rel_w + (long)(l * 2 + 1) * 128 * 128;
        const float* wr = root_w + (long)l * 128 * 128;
        k_gemm128<0, false><<<gm, 256>>>(px, w0, nullptr, py,        NN, 128, 256);
        k_gemm128<0, false><<<gm, 256>>>(px, w1, nullptr, py + 128,  NN, 128, 256);
        k_gemm128<0, false><<<gm, 256>>>(px, wr, nullptr, proot,     NN, 128, 128);
        k_gather<<<(NN * 32) / 256, 256>>>(py, proot, rgcn_b + l * 128, px);
    }

    // ---- MLP head
    k_gemm128<2, false><<<gm, 256>>>(px, mlp_w1, mlp_b1, ph, NN, 128, 128);
    k_mlp2<<<(NN * 32) / 256, 256>>>(ph, mlp_w2, mlp_b2, out);
}

// round 2
// speedup vs baseline: 1.4167x; 1.4167x over previous
#include <cuda_runtime.h>
#include <cuda_bf16.h>
#include <cstdint>

#define NN 50000
#define EE 1600000
#define DD 128
#define NB 196            // ceil(NN/256)

// ---------------- scratch (device globals; no allocation allowed) ----------
__device__ float g_x[NN * 128];      // node features
__device__ float g_y[NN * 256];      // [Y0 | Y1] per node (row stride 256)
__device__ float g_root[NN * 128];   // X @ root_w
__device__ float g_h[NN * 128];      // MLP hidden
__device__ int   g_cnt[2 * NN];      // per-relation in-degree
__device__ int   g_off[NN + 1];      // CSR offsets by dst
__device__ int   g_cur[NN];          // scatter cursors
__device__ int   g_list[EE];         // packed (src<<1)|rel, grouped by dst
__device__ float g_inv[2 * NN];      // 1/max(cnt_r,1)
__device__ int   g_loc[NN];          // block-local inclusive scan
__device__ int   g_bsum[256];
__device__ int   g_bpre[256];

__device__ __forceinline__ float lrelu(float v) { return v > 0.f ? v : 0.01f * v; }

__device__ __forceinline__ uint32_t f2tf32(float x) {
    uint32_t r;
    asm("cvt.rna.tf32.f32 %0, %1;" : "=r"(r) : "f"(x));
    return r;
}

__device__ __forceinline__ void mma_tf32(float c[4], const uint32_t a[4], const uint32_t b[2]) {
    asm volatile("mma.sync.aligned.m16n8k8.row.col.f32.tf32.tf32.f32 "
        "{%0,%1,%2,%3}, {%4,%5,%6,%7}, {%8,%9}, {%0,%1,%2,%3};"
        : "+f"(c[0]), "+f"(c[1]), "+f"(c[2]), "+f"(c[3])
        : "r"(a[0]), "r"(a[1]), "r"(a[2]), "r"(a[3]), "r"(b[0]), "r"(b[1]));
}

// ---------------- edge preprocessing ----------------------------------------
__global__ void k_zero_cnt() {
    int i = blockIdx.x * 256 + threadIdx.x;
    if (i < 2 * NN) g_cnt[i] = 0;
}

__global__ void k_hist(const int* __restrict__ ei, const int* __restrict__ et) {
    int e = blockIdx.x * 256 + threadIdx.x;
    if (e < EE) {
        int dst = ei[EE + e];
        int r   = et[e];
        atomicAdd(&g_cnt[r * NN + dst], 1);
    }
}

__global__ void k_scan1() {
    __shared__ int s[256];
    int t = threadIdx.x;
    int i = blockIdx.x * 256 + t;
    int d = 0;
    if (i < NN) d = g_cnt[i] + g_cnt[NN + i];
    s[t] = d;
    __syncthreads();
    #pragma unroll
    for (int off = 1; off < 256; off <<= 1) {
        int v = (t >= off) ? s[t - off] : 0;
        __syncthreads();
        s[t] += v;
        __syncthreads();
    }
    if (i < NN) g_loc[i] = s[t];
    if (t == 255) g_bsum[blockIdx.x] = s[255];
}

__global__ void k_scan2() {
    __shared__ int s[256];
    int t = threadIdx.x;
    int d = (t < NB) ? g_bsum[t] : 0;
    s[t] = d;
    __syncthreads();
    #pragma unroll
    for (int off = 1; off < 256; off <<= 1) {
        int v = (t >= off) ? s[t - off] : 0;
        __syncthreads();
        s[t] += v;
        __syncthreads();
    }
    g_bpre[t] = s[t] - d;   // exclusive
}

__global__ void k_scan3() {
    int i = blockIdx.x * 256 + threadIdx.x;
    if (i >= NN) return;
    int c0 = g_cnt[i], c1 = g_cnt[NN + i];
    int deg = c0 + c1;
    int excl = g_bpre[blockIdx.x] + g_loc[i] - deg;
    g_off[i] = excl;
    g_cur[i] = excl;
    g_inv[i]      = 1.0f / (c0 > 0 ? (float)c0 : 1.0f);
    g_inv[NN + i] = 1.0f / (c1 > 0 ? (float)c1 : 1.0f);
    if (i == NN - 1) g_off[NN] = excl + deg;
}

__global__ void k_fill(const int* __restrict__ ei, const int* __restrict__ et) {
    int e = blockIdx.x * 256 + threadIdx.x;
    if (e < EE) {
        int src = ei[e];
        int dst = ei[EE + e];
        int r   = et[e];
        int pos = atomicAdd(&g_cur[dst], 1);
        g_list[pos] = (src << 1) | r;
    }
}

// ---------------- tensor-core tf32 GEMM: C[M,128] (+)= act(A[M,K] @ B[K,128] + bias)
// BM=128 BN=128 BK=16, 256 threads (8 warps, each 64x32 of the output tile).
// Smem holds fragment-permuted tf32 so operand fetch is LDS.128/LDS.64, conflict-free.
// Requires K % 16 == 0.
template <int ACT, bool ACCUM>
__global__ void __launch_bounds__(256, 2)
k_tc_gemm(const float* __restrict__ A, const float* __restrict__ B,
          const float* __restrict__ bias, float* __restrict__ C,
          int M, int K, int ldc) {
    // A: 16 blocks (m16blk 0..7, k8 0..1) of 512B; thread-contiguous 4 floats
    // B: 32 blocks (n8blk 0..15, k8 0..1) of 256B; thread-contiguous 2 floats
    __shared__ uint32_t As[2][2048];
    __shared__ uint32_t Bs[2][2048];

    int tid  = threadIdx.x;
    int lane = tid & 31;
    int w    = tid >> 5;
    int wm   = w & 1;    // 0..1 : 64-row slab
    int wn   = w >> 1;   // 0..3 : 32-col slab
    int m0   = blockIdx.x * 128;
    int grp  = lane >> 2;
    int q    = lane & 3;

    float acc[4][4][4];
    #pragma unroll
    for (int i = 0; i < 4; i++)
        #pragma unroll
        for (int j = 0; j < 4; j++)
            #pragma unroll
            for (int v = 0; v < 4; v++) acc[i][j][v] = 0.f;

    auto ld_tile = [&](int k0, int st) {
        // A tile: 128 x 16 floats
        #pragma unroll
        for (int i = 0; i < 2; i++) {
            int idx = i * 256 + tid;           // 0..511
            int r   = idx >> 2;                // 0..127
            int c4  = idx & 3;                 // float4 index along k
            float4 v = make_float4(0.f, 0.f, 0.f, 0.f);
            if (m0 + r < M) v = *(const float4*)&A[(long)(m0 + r) * K + k0 + c4 * 4];
            int m16  = r >> 4;
            int rbit = (r >> 3) & 1;
            int t4   = (r & 7) * 4;
            const float* vf = (const float*)&v;
            #pragma unroll
            for (int u = 0; u < 4; u++) {
                int c  = c4 * 4 + u;           // 0..15
                int k8 = c >> 3;
                int tw = t4 + (c & 3);
                int vv = rbit + 2 * ((c >> 2) & 1);
                As[st][(m16 * 2 + k8) * 128 + tw * 4 + vv] = f2tf32(vf[u]);
            }
        }
        // B tile: 16 x 128 floats
        #pragma unroll
        for (int i = 0; i < 2; i++) {
            int idx = i * 256 + tid;           // 0..511
            int kk  = idx >> 5;                // 0..15
            int n4  = idx & 31;                // float4 index along n
            float4 v = *(const float4*)&B[(long)(k0 + kk) * 128 + n4 * 4];
            int k8   = kk >> 3;
            int vbit = (kk >> 2) & 1;
            int kb   = kk & 3;
            const float* vf = (const float*)&v;
            #pragma unroll
            for (int u = 0; u < 4; u++) {
                int n  = n4 * 4 + u;
                int tw = (n & 7) * 4 + kb;
                Bs[st][((n >> 3) * 2 + k8) * 64 + tw * 2 + vbit] = f2tf32(vf[u]);
            }
        }
    };

    auto compute = [&](int st) {
        #pragma unroll
        for (int k8 = 0; k8 < 2; k8++) {
            uint32_t af[4][4];
            uint32_t bf[4][2];
            #pragma unroll
            for (int mf = 0; mf < 4; mf++) {
                uint4 t = *(const uint4*)&As[st][((wm * 4 + mf) * 2 + k8) * 128 + lane * 4];
                af[mf][0] = t.x; af[mf][1] = t.y; af[mf][2] = t.z; af[mf][3] = t.w;
            }
            #pragma unroll
            for (int nf = 0; nf < 4; nf++) {
                uint2 t = *(const uint2*)&Bs[st][((wn * 4 + nf) * 2 + k8) * 64 + lane * 2];
                bf[nf][0] = t.x; bf[nf][1] = t.y;
            }
            #pragma unroll
            for (int mf = 0; mf < 4; mf++)
                #pragma unroll
                for (int nf = 0; nf < 4; nf++)
                    mma_tf32(acc[mf][nf], af[mf], bf[nf]);
        }
    };

    int nk = K >> 4;
    ld_tile(0, 0);
    __syncthreads();
    for (int kt = 0; kt < nk; kt++) {
        int st = kt & 1;
        if (kt + 1 < nk) ld_tile((kt + 1) * 16, st ^ 1);
        compute(st);
        __syncthreads();
    }

    // epilogue
    #pragma unroll
    for (int mf = 0; mf < 4; mf++) {
        int rbase = m0 + wm * 64 + mf * 16 + grp;
        #pragma unroll
        for (int half = 0; half < 2; half++) {
            int row = rbase + half * 8;
            if (row >= M) continue;
            #pragma unroll
            for (int nf = 0; nf < 4; nf++) {
                int col = wn * 32 + nf * 8 + q * 2;
                float v0 = acc[mf][nf][half * 2 + 0];
                float v1 = acc[mf][nf][half * 2 + 1];
                if (bias) { v0 += bias[col]; v1 += bias[col + 1]; }
                if (ACT == 1) { v0 = lrelu(v0); v1 = lrelu(v1); }
                else if (ACT == 2) { v0 = fmaxf(v0, 0.f); v1 = fmaxf(v1, 0.f); }
                long idx = (long)row * ldc + col;
                if (ACCUM) { C[idx] += v0; C[idx + 1] += v1; }
                else       { C[idx] = v0;  C[idx + 1] = v1; }
            }
        }
    }
}

// ---------------- SIMT fp32 GEMM (kept for tiny K = 5/6) ---------------------
template <int ACT, bool ACCUM>
__global__ void k_gemm128(const float* __restrict__ A, const float* __restrict__ B,
                          const float* __restrict__ bias, float* __restrict__ C,
                          int M, int K, int ldc) {
    __shared__ float As[8][128];
    __shared__ float Bs[8][128];

    int tid = threadIdx.x;
    int tx = tid & 15;
    int ty = tid >> 4;
    int m0 = blockIdx.x * 128;

    float acc[8][8];
    #pragma unroll
    for (int i = 0; i < 8; i++)
        #pragma unroll
        for (int j = 0; j < 8; j++) acc[i][j] = 0.f;

    int am = tid >> 1;
    int ak0 = (tid & 1) * 4;

    for (int k0 = 0; k0 < K; k0 += 8) {
        {
            int row = m0 + am;
            #pragma unroll
            for (int u = 0; u < 4; u++) {
                int kk = ak0 + u;
                float v = 0.f;
                if (row < M && (k0 + kk) < K) v = A[(long)row * K + k0 + kk];
                As[kk][am] = v;
            }
        }
        {
            int kk = tid >> 5;
            int n  = (tid & 31) * 4;
            #pragma unroll
            for (int u = 0; u < 4; u++) {
                float v = 0.f;
                if ((k0 + kk) < K) v = B[(long)(k0 + kk) * 128 + n + u];
                Bs[kk][n + u] = v;
            }
        }
        __syncthreads();

        #pragma unroll
        for (int kk = 0; kk < 8; kk++) {
            float a[8], b[8];
            #pragma unroll
            for (int i = 0; i < 8; i++) a[i] = As[kk][ty * 8 + i];
            #pragma unroll
            for (int j = 0; j < 8; j++) b[j] = Bs[kk][tx * 8 + j];
            #pragma unroll
            for (int i = 0; i < 8; i++)
                #pragma unroll
                for (int j = 0; j < 8; j++)
                    acc[i][j] = fmaf(a[i], b[j], acc[i][j]);
        }
        __syncthreads();
    }

    #pragma unroll
    for (int i = 0; i < 8; i++) {
        int row = m0 + ty * 8 + i;
        if (row >= M) continue;
        #pragma unroll
        for (int j = 0; j < 8; j++) {
            int col = tx * 8 + j;
            float v = acc[i][j];
            if (bias) v += bias[col];
            if (ACT == 1) v = lrelu(v);
            else if (ACT == 2) v = fmaxf(v, 0.f);
            long idx = (long)row * ldc + col;
            if (ACCUM) C[idx] += v;
            else       C[idx] = v;
        }
    }
}

// ---------------- RGCN gather/combine: one warp per destination node --------
__global__ void k_gather(const float* __restrict__ y, const float* __restrict__ root,
                         const float* __restrict__ bias, float* __restrict__ xout) {
    int gw = (blockIdx.x * blockDim.x + threadIdx.x) >> 5;
    int lane = threadIdx.x & 31;
    if (gw >= NN) return;

    int beg = g_off[gw], end = g_off[gw + 1];
    float4 a0 = make_float4(0.f, 0.f, 0.f, 0.f);
    float4 a1 = make_float4(0.f, 0.f, 0.f, 0.f);

    for (int j = beg; j < end; j++) {
        int p = __ldg(&g_list[j]);                 // uniform across warp
        const float4 v = *(const float4*)(y + (long)(p >> 1) * 256 + (p & 1) * 128 + lane * 4);
        if (p & 1) { a1.x += v.x; a1.y += v.y; a1.z += v.z; a1.w += v.w; }
        else       { a0.x += v.x; a0.y += v.y; a0.z += v.z; a0.w += v.w; }
    }

    float i0 = g_inv[gw], i1 = g_inv[NN + gw];
    long base = (long)gw * 128 + lane * 4;
    float4 rt = *(const float4*)(root + base);
    float b0 = bias[lane * 4 + 0], b1 = bias[lane * 4 + 1];
    float b2 = bias[lane * 4 + 2], b3 = bias[lane * 4 + 3];

    float4 o;
    o.x = lrelu(rt.x + b0 + a0.x * i0 + a1.x * i1);
    o.y = lrelu(rt.y + b1 + a0.y * i0 + a1.y * i1);
    o.z = lrelu(rt.z + b2 + a0.z * i0 + a1.z * i1);
    o.w = lrelu(rt.w + b3 + a0.w * i0 + a1.w * i1);
    *(float4*)(xout + base) = o;
}

// ---------------- MLP head (D=128 -> 2): one warp per node -------------------
__global__ void k_mlp2(const float* __restrict__ h, const float* __restrict__ w2,
                       const float* __restrict__ b2, float* __restrict__ out) {
    int gw = (blockIdx.x * blockDim.x + threadIdx.x) >> 5;
    int lane = threadIdx.x & 31;
    if (gw >= NN) return;
    float a0 = 0.f, a1 = 0.f;
    #pragma unroll
    for (int kk = 0; kk < 4; kk++) {
        int k = lane + kk * 32;
        float hv = h[(long)gw * 128 + k];
        a0 = fmaf(hv, w2[2 * k + 0], a0);
        a1 = fmaf(hv, w2[2 * k + 1], a1);
    }
    #pragma unroll
    for (int off = 16; off > 0; off >>= 1) {
        a0 += __shfl_down_sync(0xFFFFFFFFu, a0, off);
        a1 += __shfl_down_sync(0xFFFFFFFFu, a1, off);
    }
    if (lane == 0) {
        out[2 * gw + 0] = a0 + b2[0];
        out[2 * gw + 1] = a1 + b2[1];
    }
}

// ---------------- launch -----------------------------------------------------
extern "C" void kernel_launch(void* const* d_in, const int* in_sizes, int n_in,
                              void* d_out, int out_size) {
    const float* des     = (const float*)d_in[0];
    const float* tweets  = (const float*)d_in[1];
    const float* numf    = (const float*)d_in[2];
    const float* catf    = (const float*)d_in[3];
    const int*   ei      = (const int*)d_in[4];
    const int*   et      = (const int*)d_in[5];
    const float* des_w   = (const float*)d_in[6];
    const float* des_b   = (const float*)d_in[7];
    const float* tweet_w = (const float*)d_in[8];
    const float* tweet_b = (const float*)d_in[9];
    const float* num_w   = (const float*)d_in[10];
    const float* num_b   = (const float*)d_in[11];
    const float* cat_w   = (const float*)d_in[12];
    const float* cat_b   = (const float*)d_in[13];
    const float* rel_w   = (const float*)d_in[14];   // [2][2][128][128]
    const float* root_w  = (const float*)d_in[15];   // [2][128][128]
    const float* rgcn_b  = (const float*)d_in[16];   // [2][128]
    const float* mlp_w1  = (const float*)d_in[17];
    const float* mlp_b1  = (const float*)d_in[18];
    const float* mlp_w2  = (const float*)d_in[19];   // [128][2]
    const float* mlp_b2  = (const float*)d_in[20];
    float* out = (float*)d_out;

    float *px, *py, *proot, *ph;
    cudaGetSymbolAddress((void**)&px,    g_x);
    cudaGetSymbolAddress((void**)&py,    g_y);
    cudaGetSymbolAddress((void**)&proot, g_root);
    cudaGetSymbolAddress((void**)&ph,    g_h);

    // ---- CSR build
    k_zero_cnt<<<(2 * NN + 255) / 256, 256>>>();
    k_hist<<<EE / 256, 256>>>(ei, et);
    k_scan1<<<NB, 256>>>();
    k_scan2<<<1, 256>>>();
    k_scan3<<<NB, 256>>>();
    k_fill<<<EE / 256, 256>>>(ei, et);

    int gm = (NN + 127) / 128;

    // ---- multimodal projections: x = sum of 4 lrelu(linear)
    k_tc_gemm<1, false><<<gm, 256>>>(des,    des_w,   des_b,   px, NN, 768, 128);
    k_tc_gemm<1, true ><<<gm, 256>>>(tweets, tweet_w, tweet_b, px, NN, 768, 128);
    k_gemm128<1, true ><<<gm, 256>>>(numf,   num_w,   num_b,   px, NN, 5,   128);
    k_gemm128<1, true ><<<gm, 256>>>(catf,   cat_w,   cat_b,   px, NN, 6,   128);

    // ---- 2 RGCN layers
    for (int l = 0; l < 2; l++) {
        const float* w0 = rel_w + (long)(l * 2 + 0) * 128 * 128;
        const float* w1 = rel_w + (long)(l * 2 + 1) * 128 * 128;
        const float* wr = root_w + (long)l * 128 * 128;
        k_tc_gemm<0, false><<<gm, 256>>>(px, w0, nullptr, py,        NN, 128, 256);
        k_tc_gemm<0, false><<<gm, 256>>>(px, w1, nullptr, py + 128,  NN, 128, 256);
        k_tc_gemm<0, false><<<gm, 256>>>(px, wr, nullptr, proot,     NN, 128, 128);
        k_gather<<<(NN * 32) / 256, 256>>>(py, proot, rgcn_b + l * 128, px);
    }

    // ---- MLP head
    k_tc_gemm<2, false><<<gm, 256>>>(px, mlp_w1, mlp_b1, ph, NN, 128, 128);
    k_mlp2<<<(NN * 32) / 256, 256>>>(ph, mlp_w2, mlp_b2, out);
}

// round 4
// speedup vs baseline: 2.8979x; 2.0455x over previous
#include <cuda_runtime.h>
#include <cuda_bf16.h>
#include <cstdint>

#define NN 50000
#define EE 1600000
#define NB 196            // ceil(NN/256)

// ---------------- scratch (device globals) ----------------------------------
__device__ float g_x[NN * 128];
__device__ float g_y[NN * 256];
__device__ float g_root[NN * 128];
__device__ float g_h[NN * 128];
__device__ float g_bt[311296];       // pre-permuted tf32 weights (frag order)
__device__ int   g_cnt[2 * NN];
__device__ int   g_off[NN + 1];
__device__ int   g_cur[NN];
__device__ int   g_list[EE];
__device__ float g_inv[2 * NN];
__device__ int   g_loc[NN];
__device__ int   g_bsum[256];
__device__ int   g_bpre[256];

// BT offsets (floats/words)
#define BT_DES  0
#define BT_TWE  98304
#define BT_REL  196608        // + (l*2+r)*16384
#define BT_ROOT 262144        // + l*16384
#define BT_MLP1 294912

__device__ __forceinline__ float lrelu(float v) { return v > 0.f ? v : 0.01f * v; }

__device__ __forceinline__ uint32_t f2tf32(float x) {
    uint32_t r;
    asm("cvt.rna.tf32.f32 %0, %1;" : "=r"(r) : "f"(x));
    return r;
}

__device__ __forceinline__ void mma_tf32(float c[4], const uint32_t a[4], const uint32_t b[2]) {
    asm volatile("mma.sync.aligned.m16n8k8.row.col.f32.tf32.tf32.f32 "
        "{%0,%1,%2,%3}, {%4,%5,%6,%7}, {%8,%9}, {%0,%1,%2,%3};"
        : "+f"(c[0]), "+f"(c[1]), "+f"(c[2]), "+f"(c[3])
        : "r"(a[0]), "r"(a[1]), "r"(a[2]), "r"(a[3]), "r"(b[0]), "r"(b[1]));
}

// ---------------- edge preprocessing ----------------------------------------
__global__ void k_zero_cnt() {
    int i = blockIdx.x * 256 + threadIdx.x;
    if (i < 2 * NN) g_cnt[i] = 0;
}

__global__ void k_hist(const int* __restrict__ ei, const int* __restrict__ et) {
    int e = blockIdx.x * 256 + threadIdx.x;
    if (e < EE) {
        int dst = ei[EE + e];
        int r   = et[e];
        atomicAdd(&g_cnt[r * NN + dst], 1);
    }
}

__global__ void k_scan1() {
    __shared__ int s[256];
    int t = threadIdx.x;
    int i = blockIdx.x * 256 + t;
    int d = 0;
    if (i < NN) d = g_cnt[i] + g_cnt[NN + i];
    s[t] = d;
    __syncthreads();
    #pragma unroll
    for (int off = 1; off < 256; off <<= 1) {
        int v = (t >= off) ? s[t - off] : 0;
        __syncthreads();
        s[t] += v;
        __syncthreads();
    }
    if (i < NN) g_loc[i] = s[t];
    if (t == 255) g_bsum[blockIdx.x] = s[255];
}

__global__ void k_scan2() {
    __shared__ int s[256];
    int t = threadIdx.x;
    int d = (t < NB) ? g_bsum[t] : 0;
    s[t] = d;
    __syncthreads();
    #pragma unroll
    for (int off = 1; off < 256; off <<= 1) {
        int v = (t >= off) ? s[t - off] : 0;
        __syncthreads();
        s[t] += v;
        __syncthreads();
    }
    g_bpre[t] = s[t] - d;   // exclusive
}

__global__ void k_scan3() {
    int i = blockIdx.x * 256 + threadIdx.x;
    if (i >= NN) return;
    int c0 = g_cnt[i], c1 = g_cnt[NN + i];
    int deg = c0 + c1;
    int excl = g_bpre[blockIdx.x] + g_loc[i] - deg;
    g_off[i] = excl;
    g_cur[i] = excl;
    g_inv[i]      = 1.0f / (c0 > 0 ? (float)c0 : 1.0f);
    g_inv[NN + i] = 1.0f / (c1 > 0 ? (float)c1 : 1.0f);
    if (i == NN - 1) g_off[NN] = excl + deg;
}

__global__ void k_fill(const int* __restrict__ ei, const int* __restrict__ et) {
    int e = blockIdx.x * 256 + threadIdx.x;
    if (e < EE) {
        int src = ei[e];
        int dst = ei[EE + e];
        int r   = et[e];
        int pos = atomicAdd(&g_cur[dst], 1);
        g_list[pos] = (src << 1) | r;
    }
}

// ---------------- B prep: [K][128] fp32 -> frag-ordered tf32 blocks ----------
// Output: nk = K/16 blocks of 2048 words; block kt is the exact smem image:
//   word w: n8=w>>7, k8=(w>>6)&1, tw=(w&63)>>1, vb=w&1
//   n = n8*8 + (tw>>2); kk = k8*8 + vb*4 + (tw&3); k = kt*16+kk
__global__ void k_prep_b(const float* __restrict__ src, float* __restrict__ dst, int K) {
    int idx = blockIdx.x * 256 + threadIdx.x;
    if (idx >= K * 128) return;
    int kt = idx >> 11;
    int w  = idx & 2047;
    int n8 = w >> 7;
    int k8 = (w >> 6) & 1;
    int tw = (w & 63) >> 1;
    int vb = w & 1;
    int n  = n8 * 8 + (tw >> 2);
    int kk = k8 * 8 + vb * 4 + (tw & 3);
    int k  = kt * 16 + kk;
    dst[idx] = __uint_as_float(f2tf32(src[(size_t)k * 128 + n]));
}

// ---------------- tensor-core tf32 GEMM (mma.sync), reg-staged pipeline ------
// C[M,128] (+)= act(A[M,K] @ B + bias); Bp = pre-permuted tf32 weights.
// BM=128 BN=128 BK=16; 256 threads (8 warps, 64x32 warp tiles). K % 16 == 0.
template <int ACT, bool ACCUM>
__global__ void __launch_bounds__(256, 2)
k_tc_gemm(const float* __restrict__ A, const uint32_t* __restrict__ Bp,
          const float* __restrict__ bias, float* __restrict__ C,
          int M, int K, int ldc) {
    __shared__ uint32_t As[2][2048];
    __shared__ uint32_t Bs[2][2048];

    int tid  = threadIdx.x;
    int lane = tid & 31;
    int w    = tid >> 5;
    int wm   = w & 1;
    int wn   = w >> 1;
    int m0   = blockIdx.x * 128;
    int grp  = lane >> 2;
    int q    = lane & 3;

    float acc[4][4][4];
    #pragma unroll
    for (int i = 0; i < 4; i++)
        #pragma unroll
        for (int j = 0; j < 4; j++)
            #pragma unroll
            for (int v = 0; v < 4; v++) acc[i][j][v] = 0.f;

    uint4 ra[2], rb[2];

    auto ldg_tile = [&](int kc) {
        #pragma unroll
        for (int u = 0; u < 2; u++) {
            int unit = tid + u * 256;       // 0..511
            int row  = unit >> 2;           // 0..127
            int c4   = unit & 3;            // float4 index along k
            int ar   = m0 + row; if (ar >= M) ar = M - 1;
            ra[u] = *(const uint4*)&A[(size_t)ar * K + kc + c4 * 4];
        }
        const uint4* bp = (const uint4*)(Bp + ((size_t)(kc >> 4)) * 2048);
        rb[0] = bp[tid * 2];
        rb[1] = bp[tid * 2 + 1];
    };

    auto sts_tile = [&](int st) {
        #pragma unroll
        for (int u = 0; u < 2; u++) {
            int unit = tid + u * 256;
            int row  = unit >> 2;
            int c4   = unit & 3;
            int m16  = row >> 4;
            int rbit = (row >> 3) & 1;
            int r7   = row & 7;
            int k8   = c4 >> 1;
            int vv   = rbit + 2 * (c4 & 1);
            uint32_t key = (uint32_t)(((r7 >> 1) & 3) << 2);
            uint32_t b0  = (uint32_t)((m16 * 2 + k8) * 128 + r7 * 16 + vv);
            const float* vf = (const float*)&ra[u];
            As[st][(b0 +  0) ^ key] = f2tf32(vf[0]);
            As[st][(b0 +  4) ^ key] = f2tf32(vf[1]);
            As[st][(b0 +  8) ^ key] = f2tf32(vf[2]);
            As[st][(b0 + 12) ^ key] = f2tf32(vf[3]);
        }
        *(uint4*)&Bs[st][tid * 8]     = rb[0];
        *(uint4*)&Bs[st][tid * 8 + 4] = rb[1];
    };

    uint32_t akey = (uint32_t)(((lane >> 3) & 3) << 2);

    auto compute = [&](int st) {
        #pragma unroll
        for (int k8 = 0; k8 < 2; k8++) {
            uint32_t af[4][4];
            uint32_t bf[4][2];
            #pragma unroll
            for (int mf = 0; mf < 4; mf++) {
                uint4 t = *(const uint4*)&As[st][((uint32_t)(((wm * 4 + mf) * 2 + k8) * 128 + lane * 4)) ^ akey];
                af[mf][0] = t.x; af[mf][1] = t.y; af[mf][2] = t.z; af[mf][3] = t.w;
            }
            #pragma unroll
            for (int nf = 0; nf < 4; nf++) {
                uint2 t = *(const uint2*)&Bs[st][((wn * 4 + nf) * 2 + k8) * 64 + lane * 2];
                bf[nf][0] = t.x; bf[nf][1] = t.y;
            }
            #pragma unroll
            for (int mf = 0; mf < 4; mf++)
                #pragma unroll
                for (int nf = 0; nf < 4; nf++)
                    mma_tf32(acc[mf][nf], af[mf], bf[nf]);
        }
    };

    int nk = K >> 4;
    // prologue: stage tile0 into smem, tile1 into regs
    ldg_tile(0);
    sts_tile(0);
    if (nk > 1) ldg_tile(16);
    __syncthreads();

    for (int kt = 0; kt < nk; kt++) {
        int st = kt & 1;
        compute(st);
        if (kt + 1 < nk) {
            sts_tile(st ^ 1);                 // regs hold tile kt+1
            if (kt + 2 < nk) ldg_tile((kt + 2) * 16);
        }
        __syncthreads();
    }

    // epilogue
    #pragma unroll
    for (int mf = 0; mf < 4; mf++) {
        int rbase = m0 + wm * 64 + mf * 16 + grp;
        #pragma unroll
        for (int half = 0; half < 2; half++) {
            int row = rbase + half * 8;
            if (row >= M) continue;
            #pragma unroll
            for (int nf = 0; nf < 4; nf++) {
                int col = wn * 32 + nf * 8 + q * 2;
                float v0 = acc[mf][nf][half * 2 + 0];
                float v1 = acc[mf][nf][half * 2 + 1];
                if (bias) { v0 += bias[col]; v1 += bias[col + 1]; }
                if (ACT == 1) { v0 = lrelu(v0); v1 = lrelu(v1); }
                else if (ACT == 2) { v0 = fmaxf(v0, 0.f); v1 = fmaxf(v1, 0.f); }
                long idx = (long)row * ldc + col;
                if (ACCUM) { C[idx] += v0; C[idx + 1] += v1; }
                else       { C[idx] = v0;  C[idx + 1] = v1; }
            }
        }
    }
}

// ---------------- SIMT fp32 GEMM (tiny K = 5/6) -------------------------------
template <int ACT, bool ACCUM>
__global__ void k_gemm128(const float* __restrict__ A, const float* __restrict__ B,
                          const float* __restrict__ bias, float* __restrict__ C,
                          int M, int K, int ldc) {
    __shared__ float As[8][128];
    __shared__ float Bs[8][128];

    int tid = threadIdx.x;
    int tx = tid & 15;
    int ty = tid >> 4;
    int m0 = blockIdx.x * 128;

    float acc[8][8];
    #pragma unroll
    for (int i = 0; i < 8; i++)
        #pragma unroll
        for (int j = 0; j < 8; j++) acc[i][j] = 0.f;

    int am = tid >> 1;
    int ak0 = (tid & 1) * 4;

    for (int k0 = 0; k0 < K; k0 += 8) {
        {
            int row = m0 + am;
            #pragma unroll
            for (int u = 0; u < 4; u++) {
                int kk = ak0 + u;
                float v = 0.f;
                if (row < M && (k0 + kk) < K) v = A[(long)row * K + k0 + kk];
                As[kk][am] = v;
            }
        }
        {
            int kk = tid >> 5;
            int n  = (tid & 31) * 4;
            #pragma unroll
            for (int u = 0; u < 4; u++) {
                float v = 0.f;
                if ((k0 + kk) < K) v = B[(long)(k0 + kk) * 128 + n + u];
                Bs[kk][n + u] = v;
            }
        }
        __syncthreads();

        #pragma unroll
        for (int kk = 0; kk < 8; kk++) {
            float a[8], b[8];
            #pragma unroll
            for (int i = 0; i < 8; i++) a[i] = As[kk][ty * 8 + i];
            #pragma unroll
            for (int j = 0; j < 8; j++) b[j] = Bs[kk][tx * 8 + j];
            #pragma unroll
            for (int i = 0; i < 8; i++)
                #pragma unroll
                for (int j = 0; j < 8; j++)
                    acc[i][j] = fmaf(a[i], b[j], acc[i][j]);
        }
        __syncthreads();
    }

    #pragma unroll
    for (int i = 0; i < 8; i++) {
        int row = m0 + ty * 8 + i;
        if (row >= M) continue;
        #pragma unroll
        for (int j = 0; j < 8; j++) {
            int col = tx * 8 + j;
            float v = acc[i][j];
            if (bias) v += bias[col];
            if (ACT == 1) v = lrelu(v);
            else if (ACT == 2) v = fmaxf(v, 0.f);
            long idx = (long)row * ldc + col;
            if (ACCUM) C[idx] += v;
            else       C[idx] = v;
        }
    }
}

// ---------------- RGCN gather/combine: one warp per destination node --------
__global__ void k_gather(const float* __restrict__ y, const float* __restrict__ root,
                         const float* __restrict__ bias, float* __restrict__ xout) {
    int gw = (blockIdx.x * blockDim.x + threadIdx.x) >> 5;
    int lane = threadIdx.x & 31;
    if (gw >= NN) return;

    int beg = g_off[gw], end = g_off[gw + 1];
    float4 a0 = make_float4(0.f, 0.f, 0.f, 0.f);
    float4 a1 = make_float4(0.f, 0.f, 0.f, 0.f);

    for (int j = beg; j < end; j++) {
        int p = __ldg(&g_list[j]);
        const float4 v = *(const float4*)(y + (long)(p >> 1) * 256 + (p & 1) * 128 + lane * 4);
        if (p & 1) { a1.x += v.x; a1.y += v.y; a1.z += v.z; a1.w += v.w; }
        else       { a0.x += v.x; a0.y += v.y; a0.z += v.z; a0.w += v.w; }
    }

    float i0 = g_inv[gw], i1 = g_inv[NN + gw];
    long base = (long)gw * 128 + lane * 4;
    float4 rt = *(const float4*)(root + base);
    float b0 = bias[lane * 4 + 0], b1 = bias[lane * 4 + 1];
    float b2 = bias[lane * 4 + 2], b3 = bias[lane * 4 + 3];

    float4 o;
    o.x = lrelu(rt.x + b0 + a0.x * i0 + a1.x * i1);
    o.y = lrelu(rt.y + b1 + a0.y * i0 + a1.y * i1);
    o.z = lrelu(rt.z + b2 + a0.z * i0 + a1.z * i1);
    o.w = lrelu(rt.w + b3 + a0.w * i0 + a1.w * i1);
    *(float4*)(xout + base) = o;
}

// ---------------- MLP head (D=128 -> 2): one warp per node -------------------
__global__ void k_mlp2(const float* __restrict__ h, const float* __restrict__ w2,
                       const float* __restrict__ b2, float* __restrict__ out) {
    int gw = (blockIdx.x * blockDim.x + threadIdx.x) >> 5;
    int lane = threadIdx.x & 31;
    if (gw >= NN) return;
    float a0 = 0.f, a1 = 0.f;
    #pragma unroll
    for (int kk = 0; kk < 4; kk++) {
        int k = lane + kk * 32;
        float hv = h[(long)gw * 128 + k];
        a0 = fmaf(hv, w2[2 * k + 0], a0);
        a1 = fmaf(hv, w2[2 * k + 1], a1);
    }
    #pragma unroll
    for (int off = 16; off > 0; off >>= 1) {
        a0 += __shfl_down_sync(0xFFFFFFFFu, a0, off);
        a1 += __shfl_down_sync(0xFFFFFFFFu, a1, off);
    }
    if (lane == 0) {
        out[2 * gw + 0] = a0 + b2[0];
        out[2 * gw + 1] = a1 + b2[1];
    }
}

// ---------------- launch -----------------------------------------------------
extern "C" void kernel_launch(void* const* d_in, const int* in_sizes, int n_in,
                              void* d_out, int out_size) {
    const float* des     = (const float*)d_in[0];
    const float* tweets  = (const float*)d_in[1];
    const float* numf    = (const float*)d_in[2];
    const float* catf    = (const float*)d_in[3];
    const int*   ei      = (const int*)d_in[4];
    const int*   et      = (const int*)d_in[5];
    const float* des_w   = (const float*)d_in[6];
    const float* des_b   = (const float*)d_in[7];
    const float* tweet_w = (const float*)d_in[8];
    const float* tweet_b = (const float*)d_in[9];
    const float* num_w   = (const float*)d_in[10];
    const float* num_b   = (const float*)d_in[11];
    const float* cat_w   = (const float*)d_in[12];
    const float* cat_b   = (const float*)d_in[13];
    const float* rel_w   = (const float*)d_in[14];   // [2][2][128][128]
    const float* root_w  = (const float*)d_in[15];   // [2][128][128]
    const float* rgcn_b  = (const float*)d_in[16];   // [2][128]
    const float* mlp_w1  = (const float*)d_in[17];
    const float* mlp_b1  = (const float*)d_in[18];
    const float* mlp_w2  = (const float*)d_in[19];   // [128][2]
    const float* mlp_b2  = (const float*)d_in[20];
    float* out = (float*)d_out;

    float *px, *py, *proot, *ph, *pbt;
    cudaGetSymbolAddress((void**)&px,    g_x);
    cudaGetSymbolAddress((void**)&py,    g_y);
    cudaGetSymbolAddress((void**)&proot, g_root);
    cudaGetSymbolAddress((void**)&ph,    g_h);
    cudaGetSymbolAddress((void**)&pbt,   g_bt);
    const uint32_t* ubt = (const uint32_t*)pbt;

    // ---- pre-permute all weights into frag-ordered tf32 blocks
    k_prep_b<<<384, 256>>>(des_w,   pbt + BT_DES, 768);
    k_prep_b<<<384, 256>>>(tweet_w, pbt + BT_TWE, 768);
    for (int i = 0; i < 4; i++)
        k_prep_b<<<64, 256>>>(rel_w + (size_t)i * 16384, pbt + BT_REL + i * 16384, 128);
    for (int l = 0; l < 2; l++)
        k_prep_b<<<64, 256>>>(root_w + (size_t)l * 16384, pbt + BT_ROOT + l * 16384, 128);
    k_prep_b<<<64, 256>>>(mlp_w1, pbt + BT_MLP1, 128);

    // ---- CSR build
    k_zero_cnt<<<(2 * NN + 255) / 256, 256>>>();
    k_hist<<<EE / 256, 256>>>(ei, et);
    k_scan1<<<NB, 256>>>();
    k_scan2<<<1, 256>>>();
    k_scan3<<<NB, 256>>>();
    k_fill<<<EE / 256, 256>>>(ei, et);

    int gm = (NN + 127) / 128;

    // ---- multimodal projections
    k_tc_gemm<1, false><<<gm, 256>>>(des,    ubt + BT_DES, des_b,   px, NN, 768, 128);
    k_tc_gemm<1, true ><<<gm, 256>>>(tweets, ubt + BT_TWE, tweet_b, px, NN, 768, 128);
    k_gemm128<1, true><<<gm, 256>>>(numf, num_w, num_b, px, NN, 5, 128);
    k_gemm128<1, true><<<gm, 256>>>(catf, cat_w, cat_b, px, NN, 6, 128);

    // ---- 2 RGCN layers
    for (int l = 0; l < 2; l++) {
        const uint32_t* w0 = ubt + BT_REL + (l * 2 + 0) * 16384;
        const uint32_t* w1 = ubt + BT_REL + (l * 2 + 1) * 16384;
        const uint32_t* wr = ubt + BT_ROOT + l * 16384;
        k_tc_gemm<0, false><<<gm, 256>>>(px, w0, nullptr, py,       NN, 128, 256);
        k_tc_gemm<0, false><<<gm, 256>>>(px, w1, nullptr, py + 128, NN, 128, 256);
        k_tc_gemm<0, false><<<gm, 256>>>(px, wr, nullptr, proot,    NN, 128, 128);
        k_gather<<<(NN * 32) / 256, 256>>>(py, proot, rgcn_b + l * 128, px);
    }

    // ---- MLP head
    k_tc_gemm<2, false><<<gm, 256>>>(px, ubt + BT_MLP1, mlp_b1, ph, NN, 128, 128);
    k_mlp2<<<(NN * 32) / 256, 256>>>(ph, mlp_w2, mlp_b2, out);
}

// round 5
// speedup vs baseline: 3.4013x; 1.1737x over previous
#include <cuda_runtime.h>
#include <cuda_bf16.h>
#include <cstdint>

#define NN 50000
#define EE 1600000

// ---------------- scratch (device globals) ----------------------------------
__device__ float g_x[NN * 128];      // node features (px)
__device__ float g_h[NN * 128];      // tweets projection
__device__ float g_y[NN * 256];      // [Y0 | Y1] per node
__device__ float g_root[NN * 128];
__device__ float g_bt[311296];       // pre-permuted tf32 weights
__device__ int   g_cnt[2 * NN];
__device__ int   g_off[NN];
__device__ int   g_len[NN];
__device__ int   g_cur[NN];
__device__ int   g_list[EE];
__device__ float g_inv[2 * NN];
__device__ int   g_total;

#define BT_DES  0
#define BT_TWE  98304
#define BT_REL  196608
#define BT_ROOT 262144
#define BT_MLP1 294912

__device__ __forceinline__ float lrelu(float v) { return v > 0.f ? v : 0.01f * v; }

__device__ __forceinline__ uint32_t f2tf32(float x) {
    uint32_t r;
    asm("cvt.rna.tf32.f32 %0, %1;" : "=r"(r) : "f"(x));
    return r;
}

__device__ __forceinline__ void mma_tf32(float c[4], const uint32_t a[4], const uint32_t b[2]) {
    asm volatile("mma.sync.aligned.m16n8k8.row.col.f32.tf32.tf32.f32 "
        "{%0,%1,%2,%3}, {%4,%5,%6,%7}, {%8,%9}, {%0,%1,%2,%3};"
        : "+f"(c[0]), "+f"(c[1]), "+f"(c[2]), "+f"(c[3])
        : "r"(a[0]), "r"(a[1]), "r"(a[2]), "r"(a[3]), "r"(b[0]), "r"(b[1]));
}

// ---------------- device helpers ---------------------------------------------
__device__ __forceinline__ void dev_prep_b(const float* __restrict__ src,
                                           float* __restrict__ dst, int K, int blk) {
    int idx = blk * 256 + threadIdx.x;
    if (idx >= K * 128) return;
    int w  = idx & 2047;
    int n8 = w >> 7;
    int k8 = (w >> 6) & 1;
    int tw = (w & 63) >> 1;
    int vb = w & 1;
    int n  = n8 * 8 + (tw >> 2);
    int kk = k8 * 8 + vb * 4 + (tw & 3);
    int k  = (idx >> 11) * 16 + kk;
    dst[idx] = __uint_as_float(f2tf32(src[(size_t)k * 128 + n]));
}

__device__ __forceinline__ void dev_hist(const int* __restrict__ ei,
                                         const int* __restrict__ et, int blk) {
    int e = blk * 256 + threadIdx.x;
    if (e < EE) atomicAdd(&g_cnt[et[e] * NN + ei[EE + e]], 1);
}

__device__ __forceinline__ void dev_assign(int blk) {
    int i = blk * 256 + threadIdx.x;
    if (i >= NN) return;
    int c0 = g_cnt[i], c1 = g_cnt[NN + i];
    int deg = c0 + c1;
    int pos = atomicAdd(&g_total, deg);
    g_off[i] = pos;
    g_cur[i] = pos;
    g_len[i] = deg;
    g_inv[i]      = 1.0f / (c0 > 0 ? (float)c0 : 1.0f);
    g_inv[NN + i] = 1.0f / (c1 > 0 ? (float)c1 : 1.0f);
}

__device__ __forceinline__ void dev_fill(const int* __restrict__ ei,
                                         const int* __restrict__ et, int blk) {
    int e = blk * 256 + threadIdx.x;
    if (e < EE) {
        int pos = atomicAdd(&g_cur[ei[EE + e]], 1);
        g_list[pos] = (ei[e] << 1) | et[e];
    }
}

// ---------------- GEMM body (tf32 mma.sync, reg-staged pipeline) -------------
template <int ACT, bool ACCUM>
__device__ __forceinline__ void gemm_body(
    const float* __restrict__ A, const uint32_t* __restrict__ Bp,
    const float* __restrict__ bias, float* __restrict__ C,
    int M, int K, int ldc, int bidx,
    uint32_t (*As)[2048], uint32_t (*Bs)[2048]) {

    int tid  = threadIdx.x;
    int lane = tid & 31;
    int w    = tid >> 5;
    int wm   = w & 1;
    int wn   = w >> 1;
    int m0   = bidx * 128;
    int grp  = lane >> 2;
    int q    = lane & 3;

    float acc[4][4][4];
    #pragma unroll
    for (int i = 0; i < 4; i++)
        #pragma unroll
        for (int j = 0; j < 4; j++)
            #pragma unroll
            for (int v = 0; v < 4; v++) acc[i][j][v] = 0.f;

    uint4 ra[2], rb[2];

    auto ldg_tile = [&](int kc) {
        #pragma unroll
        for (int u = 0; u < 2; u++) {
            int unit = tid + u * 256;
            int row  = unit >> 2;
            int c4   = unit & 3;
            int ar   = m0 + row; if (ar >= M) ar = M - 1;
            ra[u] = *(const uint4*)&A[(size_t)ar * K + kc + c4 * 4];
        }
        const uint4* bp = (const uint4*)(Bp + ((size_t)(kc >> 4)) * 2048);
        rb[0] = bp[tid * 2];
        rb[1] = bp[tid * 2 + 1];
    };

    auto sts_tile = [&](int st) {
        #pragma unroll
        for (int u = 0; u < 2; u++) {
            int unit = tid + u * 256;
            int row  = unit >> 2;
            int c4   = unit & 3;
            int m16  = row >> 4;
            int rbit = (row >> 3) & 1;
            int r7   = row & 7;
            int k8   = c4 >> 1;
            int vv   = rbit + 2 * (c4 & 1);
            uint32_t key = (uint32_t)(((r7 >> 1) & 3) << 2);
            uint32_t b0  = (uint32_t)((m16 * 2 + k8) * 128 + r7 * 16 + vv);
            const float* vf = (const float*)&ra[u];
            As[st][(b0 +  0) ^ key] = f2tf32(vf[0]);
            As[st][(b0 +  4) ^ key] = f2tf32(vf[1]);
            As[st][(b0 +  8) ^ key] = f2tf32(vf[2]);
            As[st][(b0 + 12) ^ key] = f2tf32(vf[3]);
        }
        *(uint4*)&Bs[st][tid * 8]     = rb[0];
        *(uint4*)&Bs[st][tid * 8 + 4] = rb[1];
    };

    uint32_t akey = (uint32_t)(((lane >> 3) & 3) << 2);

    auto compute = [&](int st) {
        #pragma unroll
        for (int k8 = 0; k8 < 2; k8++) {
            uint32_t af[4][4];
            uint32_t bf[4][2];
            #pragma unroll
            for (int mf = 0; mf < 4; mf++) {
                uint4 t = *(const uint4*)&As[st][((uint32_t)(((wm * 4 + mf) * 2 + k8) * 128 + lane * 4)) ^ akey];
                af[mf][0] = t.x; af[mf][1] = t.y; af[mf][2] = t.z; af[mf][3] = t.w;
            }
            #pragma unroll
            for (int nf = 0; nf < 4; nf++) {
                uint2 t = *(const uint2*)&Bs[st][((wn * 4 + nf) * 2 + k8) * 64 + lane * 2];
                bf[nf][0] = t.x; bf[nf][1] = t.y;
            }
            #pragma unroll
            for (int mf = 0; mf < 4; mf++)
                #pragma unroll
                for (int nf = 0; nf < 4; nf++)
                    mma_tf32(acc[mf][nf], af[mf], bf[nf]);
        }
    };

    int nk = K >> 4;
    ldg_tile(0);
    sts_tile(0);
    if (nk > 1) ldg_tile(16);
    __syncthreads();

    for (int kt = 0; kt < nk; kt++) {
        int st = kt & 1;
        compute(st);
        if (kt + 1 < nk) {
            sts_tile(st ^ 1);
            if (kt + 2 < nk) ldg_tile((kt + 2) * 16);
        }
        __syncthreads();
    }

    #pragma unroll
    for (int mf = 0; mf < 4; mf++) {
        int rbase = m0 + wm * 64 + mf * 16 + grp;
        #pragma unroll
        for (int half = 0; half < 2; half++) {
            int row = rbase + half * 8;
            if (row >= M) continue;
            #pragma unroll
            for (int nf = 0; nf < 4; nf++) {
                int col = wn * 32 + nf * 8 + q * 2;
                float v0 = acc[mf][nf][half * 2 + 0];
                float v1 = acc[mf][nf][half * 2 + 1];
                if (bias) { v0 += bias[col]; v1 += bias[col + 1]; }
                if (ACT == 1) { v0 = lrelu(v0); v1 = lrelu(v1); }
                else if (ACT == 2) { v0 = fmaxf(v0, 0.f); v1 = fmaxf(v1, 0.f); }
                long idx = (long)row * ldc + col;
                if (ACCUM) { C[idx] += v0; C[idx + 1] += v1; }
                else       { C[idx] = v0;  C[idx + 1] = v1; }
            }
        }
    }
}

// ---------------- L1: zero counters + prep all weights -----------------------
__global__ void k_L1(const float* __restrict__ des_w, const float* __restrict__ tweet_w,
                     const float* __restrict__ rel_w, const float* __restrict__ root_w,
                     const float* __restrict__ mlp_w1, float* __restrict__ bt) {
    int bid = blockIdx.x;
    if (bid < 391) {
        int i = bid * 256 + threadIdx.x;
        if (i < 2 * NN) g_cnt[i] = 0;
        if (i == 0) g_total = 0;
        return;
    }
    int pb = bid - 391;
    if (pb < 384)       dev_prep_b(des_w,   bt + BT_DES, 768, pb);
    else if (pb < 768)  dev_prep_b(tweet_w, bt + BT_TWE, 768, pb - 384);
    else if (pb < 1024) { int i = (pb - 768) >> 6;
                          dev_prep_b(rel_w + (size_t)i * 16384, bt + BT_REL + i * 16384, 128, (pb - 768) & 63); }
    else if (pb < 1152) { int l = (pb - 1024) >> 6;
                          dev_prep_b(root_w + (size_t)l * 16384, bt + BT_ROOT + l * 16384, 128, (pb - 1024) & 63); }
    else                dev_prep_b(mlp_w1, bt + BT_MLP1, 128, pb - 1152);
}

// ---------------- L2: des-GEMM ∥ tweets-GEMM ∥ hist ---------------------------
__global__ void __launch_bounds__(256, 2)
k_L2(const float* __restrict__ des, const float* __restrict__ tweets,
     const uint32_t* __restrict__ bt, const float* __restrict__ des_b,
     const float* __restrict__ tweet_b, float* __restrict__ ox,
     float* __restrict__ oh, const int* __restrict__ ei, const int* __restrict__ et) {
    __shared__ uint32_t As[2][2048];
    __shared__ uint32_t Bs[2][2048];
    int bid = blockIdx.x;
    if (bid < 391)
        gemm_body<1, false>(des, bt + BT_DES, des_b, ox, NN, 768, 128, bid, As, Bs);
    else if (bid < 782)
        gemm_body<1, false>(tweets, bt + BT_TWE, tweet_b, oh, NN, 768, 128, bid - 391, As, Bs);
    else
        dev_hist(ei, et, bid - 782);
}

// ---------------- L3: combine (x = gx+gh+lrelu(num)+lrelu(cat)) ∥ assign -----
__global__ void k_L3(const float* __restrict__ numf, const float* __restrict__ catf,
                     const float* __restrict__ num_w, const float* __restrict__ num_b,
                     const float* __restrict__ cat_w, const float* __restrict__ cat_b,
                     const float* __restrict__ gx, const float* __restrict__ gh,
                     float* __restrict__ px) {
    int bid = blockIdx.x;
    if (bid >= 6250) { dev_assign(bid - 6250); return; }
    int wid  = threadIdx.x >> 5;
    int lane = threadIdx.x & 31;
    int row  = bid * 8 + wid;
    if (row >= NN) return;

    float nv[5], cv[6];
    #pragma unroll
    for (int k = 0; k < 5; k++) nv[k] = numf[row * 5 + k];
    #pragma unroll
    for (int k = 0; k < 6; k++) cv[k] = catf[row * 6 + k];

    float4 a = *(const float4*)&gx[(size_t)row * 128 + lane * 4];
    float4 b = *(const float4*)&gh[(size_t)row * 128 + lane * 4];
    const float* af = (const float*)&a;
    const float* bf = (const float*)&b;

    float o[4];
    #pragma unroll
    for (int u = 0; u < 4; u++) {
        int col = lane * 4 + u;
        float s = num_b[col];
        #pragma unroll
        for (int k = 0; k < 5; k++) s = fmaf(nv[k], num_w[k * 128 + col], s);
        float t = cat_b[col];
        #pragma unroll
        for (int k = 0; k < 6; k++) t = fmaf(cv[k], cat_w[k * 128 + col], t);
        o[u] = af[u] + bf[u] + lrelu(s) + lrelu(t);
    }
    *(float4*)&px[(size_t)row * 128 + lane * 4] = make_float4(o[0], o[1], o[2], o[3]);
}

// ---------------- L4/L6: fused RGCN 3-GEMMs (∥ fill on first layer) ----------
__global__ void __launch_bounds__(256, 2)
k_rgcn(const float* __restrict__ px, const uint32_t* __restrict__ w0,
       const uint32_t* __restrict__ w1, const uint32_t* __restrict__ wr,
       float* __restrict__ py, float* __restrict__ proot,
       const int* __restrict__ ei, const int* __restrict__ et) {
    __shared__ uint32_t As[2][2048];
    __shared__ uint32_t Bs[2][2048];
    int bid = blockIdx.x;
    if (bid < 391)
        gemm_body<0, false>(px, w0, nullptr, py, NN, 128, 256, bid, As, Bs);
    else if (bid < 782)
        gemm_body<0, false>(px, w1, nullptr, py + 128, NN, 128, 256, bid - 391, As, Bs);
    else if (bid < 1173)
        gemm_body<0, false>(px, wr, nullptr, proot, NN, 128, 128, bid - 782, As, Bs);
    else
        dev_fill(ei, et, bid - 1173);
}

// ---------------- gather ------------------------------------------------------
__global__ void k_gather(const float* __restrict__ y, const float* __restrict__ root,
                         const float* __restrict__ bias, float* __restrict__ xout) {
    int gw = (blockIdx.x * blockDim.x + threadIdx.x) >> 5;
    int lane = threadIdx.x & 31;
    if (gw >= NN) return;

    int beg = g_off[gw], end = beg + g_len[gw];
    float4 a0 = make_float4(0.f, 0.f, 0.f, 0.f);
    float4 a1 = make_float4(0.f, 0.f, 0.f, 0.f);

    for (int j = beg; j < end; j++) {
        int p = __ldg(&g_list[j]);
        const float4 v = *(const float4*)(y + (size_t)(p >> 1) * 256 + (p & 1) * 128 + lane * 4);
        if (p & 1) { a1.x += v.x; a1.y += v.y; a1.z += v.z; a1.w += v.w; }
        else       { a0.x += v.x; a0.y += v.y; a0.z += v.z; a0.w += v.w; }
    }

    float i0 = g_inv[gw], i1 = g_inv[NN + gw];
    size_t base = (size_t)gw * 128 + lane * 4;
    float4 rt = *(const float4*)(root + base);
    float b0 = bias[lane * 4 + 0], b1 = bias[lane * 4 + 1];
    float b2 = bias[lane * 4 + 2], b3 = bias[lane * 4 + 3];

    float4 o;
    o.x = lrelu(rt.x + b0 + a0.x * i0 + a1.x * i1);
    o.y = lrelu(rt.y + b1 + a0.y * i0 + a1.y * i1);
    o.z = lrelu(rt.z + b2 + a0.z * i0 + a1.z * i1);
    o.w = lrelu(rt.w + b3 + a0.w * i0 + a1.w * i1);
    *(float4*)(xout + base) = o;
}

// ---------------- L8: MLP1 GEMM + fused 2-wide head ---------------------------
__global__ void __launch_bounds__(256, 2)
k_mlp_head(const float* __restrict__ A, const uint32_t* __restrict__ Bp,
           const float* __restrict__ b1, const float* __restrict__ w2,
           const float* __restrict__ b2, float* __restrict__ out) {
    __shared__ uint32_t As[2][2048];
    __shared__ uint32_t Bs[2][2048];
    __shared__ float w2s[256];
    __shared__ float outs[128][2];

    int tid  = threadIdx.x;
    int lane = tid & 31;
    int w    = tid >> 5;
    int wm   = w & 1;
    int wn   = w >> 1;
    int m0   = blockIdx.x * 128;
    int grp  = lane >> 2;
    int q    = lane & 3;

    w2s[tid & 255] = w2[tid & 255];
    outs[tid >> 1][tid & 1] = 0.f;

    float acc[4][4][4];
    #pragma unroll
    for (int i = 0; i < 4; i++)
        #pragma unroll
        for (int j = 0; j < 4; j++)
            #pragma unroll
            for (int v = 0; v < 4; v++) acc[i][j][v] = 0.f;

    uint4 ra[2], rb[2];
    const int K = 128;

    auto ldg_tile = [&](int kc) {
        #pragma unroll
        for (int u = 0; u < 2; u++) {
            int unit = tid + u * 256;
            int row  = unit >> 2;
            int c4   = unit & 3;
            int ar   = m0 + row; if (ar >= NN) ar = NN - 1;
            ra[u] = *(const uint4*)&A[(size_t)ar * K + kc + c4 * 4];
        }
        const uint4* bp = (const uint4*)(Bp + ((size_t)(kc >> 4)) * 2048);
        rb[0] = bp[tid * 2];
        rb[1] = bp[tid * 2 + 1];
    };
    auto sts_tile = [&](int st) {
        #pragma unroll
        for (int u = 0; u < 2; u++) {
            int unit = tid + u * 256;
            int row  = unit >> 2;
            int c4   = unit & 3;
            int m16  = row >> 4;
            int rbit = (row >> 3) & 1;
            int r7   = row & 7;
            int k8   = c4 >> 1;
            int vv   = rbit + 2 * (c4 & 1);
            uint32_t key = (uint32_t)(((r7 >> 1) & 3) << 2);
            uint32_t b0  = (uint32_t)((m16 * 2 + k8) * 128 + r7 * 16 + vv);
            const float* vf = (const float*)&ra[u];
            As[st][(b0 +  0) ^ key] = f2tf32(vf[0]);
            As[st][(b0 +  4) ^ key] = f2tf32(vf[1]);
            As[st][(b0 +  8) ^ key] = f2tf32(vf[2]);
            As[st][(b0 + 12) ^ key] = f2tf32(vf[3]);
        }
        *(uint4*)&Bs[st][tid * 8]     = rb[0];
        *(uint4*)&Bs[st][tid * 8 + 4] = rb[1];
    };
    uint32_t akey = (uint32_t)(((lane >> 3) & 3) << 2);
    auto compute = [&](int st) {
        #pragma unroll
        for (int k8 = 0; k8 < 2; k8++) {
            uint32_t af[4][4];
            uint32_t bf[4][2];
            #pragma unroll
            for (int mf = 0; mf < 4; mf++) {
                uint4 t = *(const uint4*)&As[st][((uint32_t)(((wm * 4 + mf) * 2 + k8) * 128 + lane * 4)) ^ akey];
                af[mf][0] = t.x; af[mf][1] = t.y; af[mf][2] = t.z; af[mf][3] = t.w;
            }
            #pragma unroll
            for (int nf = 0; nf < 4; nf++) {
                uint2 t = *(const uint2*)&Bs[st][((wn * 4 + nf) * 2 + k8) * 64 + lane * 2];
                bf[nf][0] = t.x; bf[nf][1] = t.y;
            }
            #pragma unroll
            for (int mf = 0; mf < 4; mf++)
                #pragma unroll
                for (int nf = 0; nf < 4; nf++)
                    mma_tf32(acc[mf][nf], af[mf], bf[nf]);
        }
    };

    int nk = K >> 4;   // 8
    ldg_tile(0);
    sts_tile(0);
    ldg_tile(16);
    __syncthreads();
    for (int kt = 0; kt < nk; kt++) {
        int st = kt & 1;
        compute(st);
        if (kt + 1 < nk) {
            sts_tile(st ^ 1);
            if (kt + 2 < nk) ldg_tile((kt + 2) * 16);
        }
        __syncthreads();
    }

    // head: out[row] = relu(acc + b1) @ w2 + b2
    #pragma unroll
    for (int mf = 0; mf < 4; mf++) {
        #pragma unroll
        for (int half = 0; half < 2; half++) {
            int rl = wm * 64 + mf * 16 + grp + half * 8;
            float p0 = 0.f, p1 = 0.f;
            #pragma unroll
            for (int nf = 0; nf < 4; nf++) {
                #pragma unroll
                for (int v = 0; v < 2; v++) {
                    int col = wn * 32 + nf * 8 + q * 2 + v;
                    float h = fmaxf(acc[mf][nf][half * 2 + v] + b1[col], 0.f);
                    p0 = fmaf(h, w2s[col * 2 + 0], p0);
                    p1 = fmaf(h, w2s[col * 2 + 1], p1);
                }
            }
            p0 += __shfl_xor_sync(0xFFFFFFFFu, p0, 1);
            p0 += __shfl_xor_sync(0xFFFFFFFFu, p0, 2);
            p1 += __shfl_xor_sync(0xFFFFFFFFu, p1, 1);
            p1 += __shfl_xor_sync(0xFFFFFFFFu, p1, 2);
            if (q == 0) {
                atomicAdd(&outs[rl][0], p0);
                atomicAdd(&outs[rl][1], p1);
            }
        }
    }
    __syncthreads();
    int r = tid >> 1, c = tid & 1;
    int row = m0 + r;
    if (row < NN) out[row * 2 + c] = outs[r][c] + b2[c];
}

// ---------------- launch -------------------------------------------------------
extern "C" void kernel_launch(void* const* d_in, const int* in_sizes, int n_in,
                              void* d_out, int out_size) {
    const float* des     = (const float*)d_in[0];
    const float* tweets  = (const float*)d_in[1];
    const float* numf    = (const float*)d_in[2];
    const float* catf    = (const float*)d_in[3];
    const int*   ei      = (const int*)d_in[4];
    const int*   et      = (const int*)d_in[5];
    const float* des_w   = (const float*)d_in[6];
    const float* des_b   = (const float*)d_in[7];
    const float* tweet_w = (const float*)d_in[8];
    const float* tweet_b = (const float*)d_in[9];
    const float* num_w   = (const float*)d_in[10];
    const float* num_b   = (const float*)d_in[11];
    const float* cat_w   = (const float*)d_in[12];
    const float* cat_b   = (const float*)d_in[13];
    const float* rel_w   = (const float*)d_in[14];
    const float* root_w  = (const float*)d_in[15];
    const float* rgcn_b  = (const float*)d_in[16];
    const float* mlp_w1  = (const float*)d_in[17];
    const float* mlp_b1  = (const float*)d_in[18];
    const float* mlp_w2  = (const float*)d_in[19];
    const float* mlp_b2  = (const float*)d_in[20];
    float* out = (float*)d_out;

    float *px, *ph, *py, *proot, *pbt;
    cudaGetSymbolAddress((void**)&px,    g_x);
    cudaGetSymbolAddress((void**)&ph,    g_h);
    cudaGetSymbolAddress((void**)&py,    g_y);
    cudaGetSymbolAddress((void**)&proot, g_root);
    cudaGetSymbolAddress((void**)&pbt,   g_bt);
    const uint32_t* ubt = (const uint32_t*)pbt;

    // L1: zero counters ∥ prep all weights
    k_L1<<<391 + 1216, 256>>>(des_w, tweet_w, rel_w, root_w, mlp_w1, pbt);

    // L2: des-GEMM ∥ tweets-GEMM ∥ hist
    k_L2<<<782 + 6250, 256>>>(des, tweets, ubt, des_b, tweet_b, px, ph, ei, et);

    // L3: combine ∥ assign
    k_L3<<<6250 + 196, 256>>>(numf, catf, num_w, num_b, cat_w, cat_b, px, ph, px);

    // L4: RGCN layer 0 GEMMs ∥ fill
    k_rgcn<<<1173 + 6250, 256>>>(px, ubt + BT_REL, ubt + BT_REL + 16384,
                                 ubt + BT_ROOT, py, proot, ei, et);
    k_gather<<<(NN * 32) / 256, 256>>>(py, proot, rgcn_b, px);

    // L6: RGCN layer 1 GEMMs
    k_rgcn<<<1173, 256>>>(px, ubt + BT_REL + 2 * 16384, ubt + BT_REL + 3 * 16384,
                          ubt + BT_ROOT + 16384, py, proot, ei, et);
    k_gather<<<(NN * 32) / 256, 256>>>(py, proot, rgcn_b + 128, px);

    // L8: MLP1 + fused head
    k_mlp_head<<<391, 256>>>(px, ubt + BT_MLP1, mlp_b1, mlp_w2, mlp_b2, out);
}

// round 6
// speedup vs baseline: 3.4840x; 1.0243x over previous
#include <cuda_runtime.h>
#include <cuda_bf16.h>
#include <cstdint>

#define NN 50000
#define EE 1600000

// ---------------- scratch (device globals) ----------------------------------
__device__ float g_x[NN * 128];      // node features (px)
__device__ float g_h[NN * 128];      // tweets projection
__device__ float g_y[NN * 256];      // [Y0 | Y1] per node
__device__ float g_root[NN * 128];
__device__ float g_bt[311296];       // pre-permuted tf32 weights
__device__ int   g_cnt[2 * NN];
__device__ int   g_off[NN];
__device__ int   g_len[NN];
__device__ int   g_cur[NN];
__device__ int   g_list[EE];
__device__ float g_inv[2 * NN];
__device__ int   g_total;

#define BT_DES  0
#define BT_TWE  98304
#define BT_REL  196608
#define BT_ROOT 262144
#define BT_MLP1 294912

__device__ __forceinline__ float lrelu(float v) { return v > 0.f ? v : 0.01f * v; }

__device__ __forceinline__ uint32_t f2tf32(float x) {
    uint32_t r;
    asm("cvt.rna.tf32.f32 %0, %1;" : "=r"(r) : "f"(x));
    return r;
}

__device__ __forceinline__ void mma_tf32(float c[4], const uint32_t a[4], const uint32_t b[2]) {
    asm volatile("mma.sync.aligned.m16n8k8.row.col.f32.tf32.tf32.f32 "
        "{%0,%1,%2,%3}, {%4,%5,%6,%7}, {%8,%9}, {%0,%1,%2,%3};"
        : "+f"(c[0]), "+f"(c[1]), "+f"(c[2]), "+f"(c[3])
        : "r"(a[0]), "r"(a[1]), "r"(a[2]), "r"(a[3]), "r"(b[0]), "r"(b[1]));
}

// ---------------- device helpers ---------------------------------------------
__device__ __forceinline__ void dev_prep_b(const float* __restrict__ src,
                                           float* __restrict__ dst, int K, int blk) {
    int idx = blk * 256 + threadIdx.x;
    if (idx >= K * 128) return;
    int w  = idx & 2047;
    int n8 = w >> 7;
    int k8 = (w >> 6) & 1;
    int tw = (w & 63) >> 1;
    int vb = w & 1;
    int n  = n8 * 8 + (tw >> 2);
    int kk = k8 * 8 + vb * 4 + (tw & 3);
    int k  = (idx >> 11) * 16 + kk;
    dst[idx] = __uint_as_float(f2tf32(src[(size_t)k * 128 + n]));
}

__device__ __forceinline__ void dev_hist(const int* __restrict__ ei,
                                         const int* __restrict__ et, int blk) {
    int e = blk * 256 + threadIdx.x;
    if (e < EE) atomicAdd(&g_cnt[et[e] * NN + ei[EE + e]], 1);
}

__device__ __forceinline__ void dev_assign(int blk) {
    int i = blk * 256 + threadIdx.x;
    if (i >= NN) return;
    int c0 = g_cnt[i], c1 = g_cnt[NN + i];
    int deg = c0 + c1;
    int pos = atomicAdd(&g_total, deg);
    g_off[i] = pos;
    g_cur[i] = pos;
    g_len[i] = deg;
    g_inv[i]      = 1.0f / (c0 > 0 ? (float)c0 : 1.0f);
    g_inv[NN + i] = 1.0f / (c1 > 0 ? (float)c1 : 1.0f);
}

__device__ __forceinline__ void dev_fill(const int* __restrict__ ei,
                                         const int* __restrict__ et, int blk) {
    int e = blk * 256 + threadIdx.x;
    if (e < EE) {
        int pos = atomicAdd(&g_cur[ei[EE + e]], 1);
        g_list[pos] = (ei[e] << 1) | et[e];
    }
}

// ---------------- GEMM body (tf32 mma.sync, reg-staged pipeline) -------------
template <int ACT, bool ACCUM>
__device__ __forceinline__ void gemm_body(
    const float* __restrict__ A, const uint32_t* __restrict__ Bp,
    const float* __restrict__ bias, float* __restrict__ C,
    int M, int K, int ldc, int bidx,
    uint32_t (*As)[2048], uint32_t (*Bs)[2048]) {

    int tid  = threadIdx.x;
    int lane = tid & 31;
    int w    = tid >> 5;
    int wm   = w & 1;
    int wn   = w >> 1;
    int m0   = bidx * 128;
    int grp  = lane >> 2;
    int q    = lane & 3;

    float acc[4][4][4];
    #pragma unroll
    for (int i = 0; i < 4; i++)
        #pragma unroll
        for (int j = 0; j < 4; j++)
            #pragma unroll
            for (int v = 0; v < 4; v++) acc[i][j][v] = 0.f;

    uint4 ra[2], rb[2];

    auto ldg_tile = [&](int kc) {
        #pragma unroll
        for (int u = 0; u < 2; u++) {
            int unit = tid + u * 256;
            int row  = unit >> 2;
            int c4   = unit & 3;
            int ar   = m0 + row; if (ar >= M) ar = M - 1;
            ra[u] = *(const uint4*)&A[(size_t)ar * K + kc + c4 * 4];
        }
        const uint4* bp = (const uint4*)(Bp + ((size_t)(kc >> 4)) * 2048);
        rb[0] = bp[tid * 2];
        rb[1] = bp[tid * 2 + 1];
    };

    auto sts_tile = [&](int st) {
        #pragma unroll
        for (int u = 0; u < 2; u++) {
            int unit = tid + u * 256;
            int row  = unit >> 2;
            int c4   = unit & 3;
            int m16  = row >> 4;
            int rbit = (row >> 3) & 1;
            int r7   = row & 7;
            int k8   = c4 >> 1;
            int vv   = rbit + 2 * (c4 & 1);
            uint32_t key = (uint32_t)(((r7 >> 1) & 3) << 2);
            uint32_t b0  = (uint32_t)((m16 * 2 + k8) * 128 + r7 * 16 + vv);
            const float* vf = (const float*)&ra[u];
            As[st][(b0 +  0) ^ key] = f2tf32(vf[0]);
            As[st][(b0 +  4) ^ key] = f2tf32(vf[1]);
            As[st][(b0 +  8) ^ key] = f2tf32(vf[2]);
            As[st][(b0 + 12) ^ key] = f2tf32(vf[3]);
        }
        *(uint4*)&Bs[st][tid * 8]     = rb[0];
        *(uint4*)&Bs[st][tid * 8 + 4] = rb[1];
    };

    uint32_t akey = (uint32_t)(((lane >> 3) & 3) << 2);

    auto compute = [&](int st) {
        #pragma unroll
        for (int k8 = 0; k8 < 2; k8++) {
            uint32_t af[4][4];
            uint32_t bf[4][2];
            #pragma unroll
            for (int mf = 0; mf < 4; mf++) {
                uint4 t = *(const uint4*)&As[st][((uint32_t)(((wm * 4 + mf) * 2 + k8) * 128 + lane * 4)) ^ akey];
                af[mf][0] = t.x; af[mf][1] = t.y; af[mf][2] = t.z; af[mf][3] = t.w;
            }
            #pragma unroll
            for (int nf = 0; nf < 4; nf++) {
                uint2 t = *(const uint2*)&Bs[st][((wn * 4 + nf) * 2 + k8) * 64 + lane * 2];
                bf[nf][0] = t.x; bf[nf][1] = t.y;
            }
            #pragma unroll
            for (int mf = 0; mf < 4; mf++)
                #pragma unroll
                for (int nf = 0; nf < 4; nf++)
                    mma_tf32(acc[mf][nf], af[mf], bf[nf]);
        }
    };

    int nk = K >> 4;
    ldg_tile(0);
    sts_tile(0);
    if (nk > 1) ldg_tile(16);
    __syncthreads();

    for (int kt = 0; kt < nk; kt++) {
        int st = kt & 1;
        compute(st);
        if (kt + 1 < nk) {
            sts_tile(st ^ 1);
            if (kt + 2 < nk) ldg_tile((kt + 2) * 16);
        }
        __syncthreads();
    }

    #pragma unroll
    for (int mf = 0; mf < 4; mf++) {
        int rbase = m0 + wm * 64 + mf * 16 + grp;
        #pragma unroll
        for (int half = 0; half < 2; half++) {
            int row = rbase + half * 8;
            if (row >= M) continue;
            #pragma unroll
            for (int nf = 0; nf < 4; nf++) {
                int col = wn * 32 + nf * 8 + q * 2;
                float v0 = acc[mf][nf][half * 2 + 0];
                float v1 = acc[mf][nf][half * 2 + 1];
                if (bias) { v0 += bias[col]; v1 += bias[col + 1]; }
                if (ACT == 1) { v0 = lrelu(v0); v1 = lrelu(v1); }
                else if (ACT == 2) { v0 = fmaxf(v0, 0.f); v1 = fmaxf(v1, 0.f); }
                long idx = (long)row * ldc + col;
                if (ACCUM) { C[idx] += v0; C[idx + 1] += v1; }
                else       { C[idx] = v0;  C[idx + 1] = v1; }
            }
        }
    }
}

// ---------------- L1: zero counters + prep all weights -----------------------
__global__ void k_L1(const float* __restrict__ des_w, const float* __restrict__ tweet_w,
                     const float* __restrict__ rel_w, const float* __restrict__ root_w,
                     const float* __restrict__ mlp_w1, float* __restrict__ bt) {
    int bid = blockIdx.x;
    if (bid < 391) {
        int i = bid * 256 + threadIdx.x;
        if (i < 2 * NN) g_cnt[i] = 0;
        if (i == 0) g_total = 0;
        return;
    }
    int pb = bid - 391;
    if (pb < 384)       dev_prep_b(des_w,   bt + BT_DES, 768, pb);
    else if (pb < 768)  dev_prep_b(tweet_w, bt + BT_TWE, 768, pb - 384);
    else if (pb < 1024) { int i = (pb - 768) >> 6;
                          dev_prep_b(rel_w + (size_t)i * 16384, bt + BT_REL + i * 16384, 128, (pb - 768) & 63); }
    else if (pb < 1152) { int l = (pb - 1024) >> 6;
                          dev_prep_b(root_w + (size_t)l * 16384, bt + BT_ROOT + l * 16384, 128, (pb - 1024) & 63); }
    else                dev_prep_b(mlp_w1, bt + BT_MLP1, 128, pb - 1152);
}

// ---------------- L2: des-GEMM ∥ tweets-GEMM ∥ hist ---------------------------
__global__ void __launch_bounds__(256, 2)
k_L2(const float* __restrict__ des, const float* __restrict__ tweets,
     const uint32_t* __restrict__ bt, const float* __restrict__ des_b,
     const float* __restrict__ tweet_b, float* __restrict__ ox,
     float* __restrict__ oh, const int* __restrict__ ei, const int* __restrict__ et) {
    __shared__ uint32_t As[2][2048];
    __shared__ uint32_t Bs[2][2048];
    int bid = blockIdx.x;
    if (bid < 391)
        gemm_body<1, false>(des, bt + BT_DES, des_b, ox, NN, 768, 128, bid, As, Bs);
    else if (bid < 782)
        gemm_body<1, false>(tweets, bt + BT_TWE, tweet_b, oh, NN, 768, 128, bid - 391, As, Bs);
    else
        dev_hist(ei, et, bid - 782);
}

// ---------------- L3: combine (x = gx+gh+lrelu(num)+lrelu(cat)) ∥ assign -----
__global__ void k_L3(const float* __restrict__ numf, const float* __restrict__ catf,
                     const float* __restrict__ num_w, const float* __restrict__ num_b,
                     const float* __restrict__ cat_w, const float* __restrict__ cat_b,
                     const float* __restrict__ gx, const float* __restrict__ gh,
                     float* __restrict__ px) {
    int bid = blockIdx.x;
    if (bid >= 6250) { dev_assign(bid - 6250); return; }
    int wid  = threadIdx.x >> 5;
    int lane = threadIdx.x & 31;
    int row  = bid * 8 + wid;
    if (row >= NN) return;

    float nv[5], cv[6];
    #pragma unroll
    for (int k = 0; k < 5; k++) nv[k] = numf[row * 5 + k];
    #pragma unroll
    for (int k = 0; k < 6; k++) cv[k] = catf[row * 6 + k];

    float4 a = *(const float4*)&gx[(size_t)row * 128 + lane * 4];
    float4 b = *(const float4*)&gh[(size_t)row * 128 + lane * 4];
    const float* af = (const float*)&a;
    const float* bf = (const float*)&b;

    float o[4];
    #pragma unroll
    for (int u = 0; u < 4; u++) {
        int col = lane * 4 + u;
        float s = num_b[col];
        #pragma unroll
        for (int k = 0; k < 5; k++) s = fmaf(nv[k], num_w[k * 128 + col], s);
        float t = cat_b[col];
        #pragma unroll
        for (int k = 0; k < 6; k++) t = fmaf(cv[k], cat_w[k * 128 + col], t);
        o[u] = af[u] + bf[u] + lrelu(s) + lrelu(t);
    }
    *(float4*)&px[(size_t)row * 128 + lane * 4] = make_float4(o[0], o[1], o[2], o[3]);
}

// ---------------- RGCN multi-B GEMM: A resident in smem, 3 B phases ----------
// dyn smem: A = 8 ktiles x 2048 words (64KB), B = 2 x 2048 words (16KB)
__global__ void __launch_bounds__(256, 2)
k_rgcn3(const float* __restrict__ px,
        const uint32_t* __restrict__ b0p, const uint32_t* __restrict__ b1p,
        const uint32_t* __restrict__ b2p,
        float* __restrict__ py, float* __restrict__ proot,
        const int* __restrict__ ei, const int* __restrict__ et) {
    extern __shared__ uint32_t dsm[];
    int bid = blockIdx.x;
    if (bid >= 391) { dev_fill(ei, et, bid - 391); return; }

    uint32_t* Asm = dsm;             // 16384 words
    uint32_t* Bsm = dsm + 16384;     // 4096 words

    int tid  = threadIdx.x;
    int lane = tid & 31;
    int w    = tid >> 5;
    int wm   = w & 1;
    int wn   = w >> 1;
    int m0   = bid * 128;
    int grp  = lane >> 2;
    int q    = lane & 3;

    // ---- load A fully (8 ktiles), convert + frag-permute into smem
    #pragma unroll
    for (int kt = 0; kt < 8; kt++) {
        #pragma unroll
        for (int u = 0; u < 2; u++) {
            int unit = tid + u * 256;
            int row  = unit >> 2;
            int c4   = unit & 3;
            int ar   = m0 + row; if (ar >= NN) ar = NN - 1;
            uint4 ra = *(const uint4*)&px[(size_t)ar * 128 + kt * 16 + c4 * 4];
            int m16  = row >> 4;
            int rbit = (row >> 3) & 1;
            int r7   = row & 7;
            int k8   = c4 >> 1;
            int vv   = rbit + 2 * (c4 & 1);
            uint32_t key = (uint32_t)(((r7 >> 1) & 3) << 2);
            uint32_t b0  = (uint32_t)(kt * 2048 + (m16 * 2 + k8) * 128 + r7 * 16 + vv);
            const float* vf = (const float*)&ra;
            Asm[(b0 +  0) ^ key] = f2tf32(vf[0]);
            Asm[(b0 +  4) ^ key] = f2tf32(vf[1]);
            Asm[(b0 +  8) ^ key] = f2tf32(vf[2]);
            Asm[(b0 + 12) ^ key] = f2tf32(vf[3]);
        }
    }
    __syncthreads();

    const uint32_t* bsel[3] = { b0p, b1p, b2p };
    float*          csel[3] = { py, py + 128, proot };
    int             lsel[3] = { 256, 256, 128 };

    uint32_t akey = (uint32_t)(((lane >> 3) & 3) << 2);
    uint4 rb[2];

    #pragma unroll
    for (int b = 0; b < 3; b++) {
        const uint32_t* Bp = bsel[b];
        float* C = csel[b];
        int ldc = lsel[b];

        float acc[4][4][4];
        #pragma unroll
        for (int i = 0; i < 4; i++)
            #pragma unroll
            for (int j = 0; j < 4; j++)
                #pragma unroll
                for (int v = 0; v < 4; v++) acc[i][j][v] = 0.f;

        auto ldg_b = [&](int kt) {
            const uint4* bp = (const uint4*)(Bp + (size_t)kt * 2048);
            rb[0] = bp[tid * 2];
            rb[1] = bp[tid * 2 + 1];
        };
        auto sts_b = [&](int st) {
            *(uint4*)&Bsm[st * 2048 + tid * 8]     = rb[0];
            *(uint4*)&Bsm[st * 2048 + tid * 8 + 4] = rb[1];
        };
        auto compute = [&](int kt, int st) {
            #pragma unroll
            for (int k8 = 0; k8 < 2; k8++) {
                uint32_t af[4][4];
                uint32_t bf[4][2];
                #pragma unroll
                for (int mf = 0; mf < 4; mf++) {
                    uint4 t = *(const uint4*)&Asm[((uint32_t)(kt * 2048 + ((wm * 4 + mf) * 2 + k8) * 128 + lane * 4)) ^ akey];
                    af[mf][0] = t.x; af[mf][1] = t.y; af[mf][2] = t.z; af[mf][3] = t.w;
                }
                #pragma unroll
                for (int nf = 0; nf < 4; nf++) {
                    uint2 t = *(const uint2*)&Bsm[st * 2048 + ((wn * 4 + nf) * 2 + k8) * 64 + lane * 2];
                    bf[nf][0] = t.x; bf[nf][1] = t.y;
                }
                #pragma unroll
                for (int mf = 0; mf < 4; mf++)
                    #pragma unroll
                    for (int nf = 0; nf < 4; nf++)
                        mma_tf32(acc[mf][nf], af[mf], bf[nf]);
            }
        };

        ldg_b(0);
        sts_b(0);
        ldg_b(1);
        __syncthreads();
        #pragma unroll
        for (int kt = 0; kt < 8; kt++) {
            int st = kt & 1;
            compute(kt, st);
            if (kt + 1 < 8) {
                sts_b(st ^ 1);
                if (kt + 2 < 8) ldg_b(kt + 2);
            }
            __syncthreads();
        }

        #pragma unroll
        for (int mf = 0; mf < 4; mf++) {
            int rbase = m0 + wm * 64 + mf * 16 + grp;
            #pragma unroll
            for (int half = 0; half < 2; half++) {
                int row = rbase + half * 8;
                if (row >= NN) continue;
                #pragma unroll
                for (int nf = 0; nf < 4; nf++) {
                    int col = wn * 32 + nf * 8 + q * 2;
                    long idx = (long)row * ldc + col;
                    C[idx]     = acc[mf][nf][half * 2 + 0];
                    C[idx + 1] = acc[mf][nf][half * 2 + 1];
                }
            }
        }
    }
}

// ---------------- gather ------------------------------------------------------
__global__ void k_gather(const float* __restrict__ y, const float* __restrict__ root,
                         const float* __restrict__ bias, float* __restrict__ xout) {
    int gw = (blockIdx.x * blockDim.x + threadIdx.x) >> 5;
    int lane = threadIdx.x & 31;
    if (gw >= NN) return;

    int beg = g_off[gw], end = beg + g_len[gw];
    float4 a0 = make_float4(0.f, 0.f, 0.f, 0.f);
    float4 a1 = make_float4(0.f, 0.f, 0.f, 0.f);

    for (int j = beg; j < end; j++) {
        int p = __ldg(&g_list[j]);
        const float4 v = *(const float4*)(y + (size_t)(p >> 1) * 256 + (p & 1) * 128 + lane * 4);
        if (p & 1) { a1.x += v.x; a1.y += v.y; a1.z += v.z; a1.w += v.w; }
        else       { a0.x += v.x; a0.y += v.y; a0.z += v.z; a0.w += v.w; }
    }

    float i0 = g_inv[gw], i1 = g_inv[NN + gw];
    size_t base = (size_t)gw * 128 + lane * 4;
    float4 rt = *(const float4*)(root + base);
    float b0 = bias[lane * 4 + 0], b1 = bias[lane * 4 + 1];
    float b2 = bias[lane * 4 + 2], b3 = bias[lane * 4 + 3];

    float4 o;
    o.x = lrelu(rt.x + b0 + a0.x * i0 + a1.x * i1);
    o.y = lrelu(rt.y + b1 + a0.y * i0 + a1.y * i1);
    o.z = lrelu(rt.z + b2 + a0.z * i0 + a1.z * i1);
    o.w = lrelu(rt.w + b3 + a0.w * i0 + a1.w * i1);
    *(float4*)(xout + base) = o;
}

// ---------------- L8: MLP1 GEMM + fused 2-wide head ---------------------------
__global__ void __launch_bounds__(256, 2)
k_mlp_head(const float* __restrict__ A, const uint32_t* __restrict__ Bp,
           const float* __restrict__ b1, const float* __restrict__ w2,
           const float* __restrict__ b2, float* __restrict__ out) {
    __shared__ uint32_t As[2][2048];
    __shared__ uint32_t Bs[2][2048];
    __shared__ float w2s[256];
    __shared__ float outs[128][2];

    int tid  = threadIdx.x;
    int lane = tid & 31;
    int w    = tid >> 5;
    int wm   = w & 1;
    int wn   = w >> 1;
    int m0   = blockIdx.x * 128;
    int grp  = lane >> 2;
    int q    = lane & 3;

    w2s[tid & 255] = w2[tid & 255];
    outs[tid >> 1][tid & 1] = 0.f;

    float acc[4][4][4];
    #pragma unroll
    for (int i = 0; i < 4; i++)
        #pragma unroll
        for (int j = 0; j < 4; j++)
            #pragma unroll
            for (int v = 0; v < 4; v++) acc[i][j][v] = 0.f;

    uint4 ra[2], rb[2];
    const int K = 128;

    auto ldg_tile = [&](int kc) {
        #pragma unroll
        for (int u = 0; u < 2; u++) {
            int unit = tid + u * 256;
            int row  = unit >> 2;
            int c4   = unit & 3;
            int ar   = m0 + row; if (ar >= NN) ar = NN - 1;
            ra[u] = *(const uint4*)&A[(size_t)ar * K + kc + c4 * 4];
        }
        const uint4* bp = (const uint4*)(Bp + ((size_t)(kc >> 4)) * 2048);
        rb[0] = bp[tid * 2];
        rb[1] = bp[tid * 2 + 1];
    };
    auto sts_tile = [&](int st) {
        #pragma unroll
        for (int u = 0; u < 2; u++) {
            int unit = tid + u * 256;
            int row  = unit >> 2;
            int c4   = unit & 3;
            int m16  = row >> 4;
            int rbit = (row >> 3) & 1;
            int r7   = row & 7;
            int k8   = c4 >> 1;
            int vv   = rbit + 2 * (c4 & 1);
            uint32_t key = (uint32_t)(((r7 >> 1) & 3) << 2);
            uint32_t b0  = (uint32_t)((m16 * 2 + k8) * 128 + r7 * 16 + vv);
            const float* vf = (const float*)&ra[u];
            As[st][(b0 +  0) ^ key] = f2tf32(vf[0]);
            As[st][(b0 +  4) ^ key] = f2tf32(vf[1]);
            As[st][(b0 +  8) ^ key] = f2tf32(vf[2]);
            As[st][(b0 + 12) ^ key] = f2tf32(vf[3]);
        }
        *(uint4*)&Bs[st][tid * 8]     = rb[0];
        *(uint4*)&Bs[st][tid * 8 + 4] = rb[1];
    };
    uint32_t akey = (uint32_t)(((lane >> 3) & 3) << 2);
    auto compute = [&](int st) {
        #pragma unroll
        for (int k8 = 0; k8 < 2; k8++) {
            uint32_t af[4][4];
            uint32_t bf[4][2];
            #pragma unroll
            for (int mf = 0; mf < 4; mf++) {
                uint4 t = *(const uint4*)&As[st][((uint32_t)(((wm * 4 + mf) * 2 + k8) * 128 + lane * 4)) ^ akey];
                af[mf][0] = t.x; af[mf][1] = t.y; af[mf][2] = t.z; af[mf][3] = t.w;
            }
            #pragma unroll
            for (int nf = 0; nf < 4; nf++) {
                uint2 t = *(const uint2*)&Bs[st][((wn * 4 + nf) * 2 + k8) * 64 + lane * 2];
                bf[nf][0] = t.x; bf[nf][1] = t.y;
            }
            #pragma unroll
            for (int mf = 0; mf < 4; mf++)
                #pragma unroll
                for (int nf = 0; nf < 4; nf++)
                    mma_tf32(acc[mf][nf], af[mf], bf[nf]);
        }
    };

    int nk = K >> 4;   // 8
    ldg_tile(0);
    sts_tile(0);
    ldg_tile(16);
    __syncthreads();
    for (int kt = 0; kt < nk; kt++) {
        int st = kt & 1;
        compute(st);
        if (kt + 1 < nk) {
            sts_tile(st ^ 1);
            if (kt + 2 < nk) ldg_tile((kt + 2) * 16);
        }
        __syncthreads();
    }

    // head: out[row] = relu(acc + b1) @ w2 + b2
    #pragma unroll
    for (int mf = 0; mf < 4; mf++) {
        #pragma unroll
        for (int half = 0; half < 2; half++) {
            int rl = wm * 64 + mf * 16 + grp + half * 8;
            float p0 = 0.f, p1 = 0.f;
            #pragma unroll
            for (int nf = 0; nf < 4; nf++) {
                #pragma unroll
                for (int v = 0; v < 2; v++) {
                    int col = wn * 32 + nf * 8 + q * 2 + v;
                    float h = fmaxf(acc[mf][nf][half * 2 + v] + b1[col], 0.f);
                    p0 = fmaf(h, w2s[col * 2 + 0], p0);
                    p1 = fmaf(h, w2s[col * 2 + 1], p1);
                }
            }
            p0 += __shfl_xor_sync(0xFFFFFFFFu, p0, 1);
            p0 += __shfl_xor_sync(0xFFFFFFFFu, p0, 2);
            p1 += __shfl_xor_sync(0xFFFFFFFFu, p1, 1);
            p1 += __shfl_xor_sync(0xFFFFFFFFu, p1, 2);
            if (q == 0) {
                atomicAdd(&outs[rl][0], p0);
                atomicAdd(&outs[rl][1], p1);
            }
        }
    }
    __syncthreads();
    int r = tid >> 1, c = tid & 1;
    int row = m0 + r;
    if (row < NN) out[row * 2 + c] = outs[r][c] + b2[c];
}

// ---------------- launch -------------------------------------------------------
#define RGCN_SMEM 81920

extern "C" void kernel_launch(void* const* d_in, const int* in_sizes, int n_in,
                              void* d_out, int out_size) {
    const float* des     = (const float*)d_in[0];
    const float* tweets  = (const float*)d_in[1];
    const float* numf    = (const float*)d_in[2];
    const float* catf    = (const float*)d_in[3];
    const int*   ei      = (const int*)d_in[4];
    const int*   et      = (const int*)d_in[5];
    const float* des_w   = (const float*)d_in[6];
    const float* des_b   = (const float*)d_in[7];
    const float* tweet_w = (const float*)d_in[8];
    const float* tweet_b = (const float*)d_in[9];
    const float* num_w   = (const float*)d_in[10];
    const float* num_b   = (const float*)d_in[11];
    const float* cat_w   = (const float*)d_in[12];
    const float* cat_b   = (const float*)d_in[13];
    const float* rel_w   = (const float*)d_in[14];
    const float* root_w  = (const float*)d_in[15];
    const float* rgcn_b  = (const float*)d_in[16];
    const float* mlp_w1  = (const float*)d_in[17];
    const float* mlp_b1  = (const float*)d_in[18];
    const float* mlp_w2  = (const float*)d_in[19];
    const float* mlp_b2  = (const float*)d_in[20];
    float* out = (float*)d_out;

    float *px, *ph, *py, *proot, *pbt;
    cudaGetSymbolAddress((void**)&px,    g_x);
    cudaGetSymbolAddress((void**)&ph,    g_h);
    cudaGetSymbolAddress((void**)&py,    g_y);
    cudaGetSymbolAddress((void**)&proot, g_root);
    cudaGetSymbolAddress((void**)&pbt,   g_bt);
    const uint32_t* ubt = (const uint32_t*)pbt;

    cudaFuncSetAttribute(k_rgcn3, cudaFuncAttributeMaxDynamicSharedMemorySize, RGCN_SMEM);

    // L1: zero counters ∥ prep all weights
    k_L1<<<391 + 1216, 256>>>(des_w, tweet_w, rel_w, root_w, mlp_w1, pbt);

    // L2: des-GEMM ∥ tweets-GEMM ∥ hist
    k_L2<<<782 + 6250, 256>>>(des, tweets, ubt, des_b, tweet_b, px, ph, ei, et);

    // L3: combine ∥ assign
    k_L3<<<6250 + 196, 256>>>(numf, catf, num_w, num_b, cat_w, cat_b, px, ph, px);

    // L4: RGCN layer 0 (A-resident 3-GEMM) ∥ fill
    k_rgcn3<<<391 + 6250, 256, RGCN_SMEM>>>(px, ubt + BT_REL, ubt + BT_REL + 16384,
                                            ubt + BT_ROOT, py, proot, ei, et);
    k_gather<<<(NN * 32) / 256, 256>>>(py, proot, rgcn_b, px);

    // L6: RGCN layer 1
    k_rgcn3<<<391, 256, RGCN_SMEM>>>(px, ubt + BT_REL + 2 * 16384, ubt + BT_REL + 3 * 16384,
                                     ubt + BT_ROOT + 16384, py, proot, ei, et);
    k_gather<<<(NN * 32) / 256, 256>>>(py, proot, rgcn_b + 128, px);

    // L8: MLP1 + fused head
    k_mlp_head<<<391, 256>>>(px, ubt + BT_MLP1, mlp_b1, mlp_w2, mlp_b2, out);
}

// round 7
// speedup vs baseline: 3.5314x; 1.0136x over previous
#include <cuda_runtime.h>
#include <cuda_bf16.h>
#include <cstdint>

#define NN 50000
#define EE 1600000

// ---------------- scratch (device globals) ----------------------------------
__device__ float g_x[NN * 128];      // node features (px)
__device__ float g_h[NN * 128];      // tweets projection
__device__ float g_y[NN * 256];      // [Y0 | Y1] per node
__device__ float g_root[NN * 128];
__device__ float g_bt[311296];       // pre-permuted tf32 weights
__device__ int   g_cnt[2 * NN];
__device__ int   g_off[NN];
__device__ int   g_len[NN];
__device__ int   g_cur[NN];
__device__ int   g_list[EE];
__device__ float g_inv[2 * NN];
__device__ int   g_total;

#define BT_DES  0
#define BT_TWE  98304
#define BT_REL  196608
#define BT_ROOT 262144
#define BT_MLP1 294912

__device__ __forceinline__ float lrelu(float v) { return v > 0.f ? v : 0.01f * v; }

__device__ __forceinline__ uint32_t f2tf32(float x) {
    uint32_t r;
    asm("cvt.rna.tf32.f32 %0, %1;" : "=r"(r) : "f"(x));
    return r;
}

__device__ __forceinline__ void mma_tf32(float c[4], const uint32_t a[4], const uint32_t b[2]) {
    asm volatile("mma.sync.aligned.m16n8k8.row.col.f32.tf32.tf32.f32 "
        "{%0,%1,%2,%3}, {%4,%5,%6,%7}, {%8,%9}, {%0,%1,%2,%3};"
        : "+f"(c[0]), "+f"(c[1]), "+f"(c[2]), "+f"(c[3])
        : "r"(a[0]), "r"(a[1]), "r"(a[2]), "r"(a[3]), "r"(b[0]), "r"(b[1]));
}

// ---------------- device helpers ---------------------------------------------
__device__ __forceinline__ void dev_prep_b(const float* __restrict__ src,
                                           float* __restrict__ dst, int K, int blk) {
    int idx = blk * 256 + threadIdx.x;
    if (idx >= K * 128) return;
    int w  = idx & 2047;
    int n8 = w >> 7;
    int k8 = (w >> 6) & 1;
    int tw = (w & 63) >> 1;
    int vb = w & 1;
    int n  = n8 * 8 + (tw >> 2);
    int kk = k8 * 8 + vb * 4 + (tw & 3);
    int k  = (idx >> 11) * 16 + kk;
    dst[idx] = __uint_as_float(f2tf32(src[(size_t)k * 128 + n]));
}

__device__ __forceinline__ void dev_hist(const int* __restrict__ ei,
                                         const int* __restrict__ et, int blk) {
    int e = blk * 256 + threadIdx.x;
    if (e < EE) atomicAdd(&g_cnt[et[e] * NN + ei[EE + e]], 1);
}

__device__ __forceinline__ void dev_assign(int blk) {
    int i = blk * 256 + threadIdx.x;
    if (i >= NN) return;
    int c0 = g_cnt[i], c1 = g_cnt[NN + i];
    int deg = c0 + c1;
    int pos = atomicAdd(&g_total, deg);
    g_off[i] = pos;
    g_cur[i] = pos;
    g_len[i] = deg;
    g_inv[i]      = 1.0f / (c0 > 0 ? (float)c0 : 1.0f);
    g_inv[NN + i] = 1.0f / (c1 > 0 ? (float)c1 : 1.0f);
}

__device__ __forceinline__ void dev_fill(const int* __restrict__ ei,
                                         const int* __restrict__ et, int blk) {
    int e = blk * 256 + threadIdx.x;
    if (e < EE) {
        int pos = atomicAdd(&g_cur[ei[EE + e]], 1);
        g_list[pos] = (ei[e] << 1) | et[e];
    }
}

// ---------------- GEMM body (tf32 mma.sync, A smem-staged, B gmem-direct) ----
template <int ACT, bool ACCUM>
__device__ __forceinline__ void gemm_body(
    const float* __restrict__ A, const uint32_t* __restrict__ Bp,
    const float* __restrict__ bias, float* __restrict__ C,
    int M, int K, int ldc, int bidx,
    uint32_t (*As)[2048]) {

    int tid  = threadIdx.x;
    int lane = tid & 31;
    int w    = tid >> 5;
    int wm   = w & 1;
    int wn   = w >> 1;
    int m0   = bidx * 128;
    int grp  = lane >> 2;
    int q    = lane & 3;

    float acc[4][4][4];
    #pragma unroll
    for (int i = 0; i < 4; i++)
        #pragma unroll
        for (int j = 0; j < 4; j++)
            #pragma unroll
            for (int v = 0; v < 4; v++) acc[i][j][v] = 0.f;

    uint4 ra[2];

    auto ldg_tile = [&](int kc) {
        #pragma unroll
        for (int u = 0; u < 2; u++) {
            int unit = tid + u * 256;
            int row  = unit >> 2;
            int c4   = unit & 3;
            int ar   = m0 + row; if (ar >= M) ar = M - 1;
            ra[u] = *(const uint4*)&A[(size_t)ar * K + kc + c4 * 4];
        }
    };

    auto sts_tile = [&](int st) {
        #pragma unroll
        for (int u = 0; u < 2; u++) {
            int unit = tid + u * 256;
            int row  = unit >> 2;
            int c4   = unit & 3;
            int m16  = row >> 4;
            int rbit = (row >> 3) & 1;
            int r7   = row & 7;
            int k8   = c4 >> 1;
            int vv   = rbit + 2 * (c4 & 1);
            uint32_t key = (uint32_t)(((r7 >> 1) & 3) << 2);
            uint32_t b0  = (uint32_t)((m16 * 2 + k8) * 128 + r7 * 16 + vv);
            const float* vf = (const float*)&ra[u];
            As[st][(b0 +  0) ^ key] = f2tf32(vf[0]);
            As[st][(b0 +  4) ^ key] = f2tf32(vf[1]);
            As[st][(b0 +  8) ^ key] = f2tf32(vf[2]);
            As[st][(b0 + 12) ^ key] = f2tf32(vf[3]);
        }
    };

    uint32_t akey = (uint32_t)(((lane >> 3) & 3) << 2);

    auto compute = [&](int kt, int st) {
        const uint32_t* bbase = Bp + (size_t)kt * 2048;
        #pragma unroll
        for (int k8 = 0; k8 < 2; k8++) {
            uint32_t af[4][4];
            uint2 bf[4];
            #pragma unroll
            for (int nf = 0; nf < 4; nf++)
                bf[nf] = *(const uint2*)&bbase[((wn * 4 + nf) * 2 + k8) * 64 + lane * 2];
            #pragma unroll
            for (int mf = 0; mf < 4; mf++) {
                uint4 t = *(const uint4*)&As[st][((uint32_t)(((wm * 4 + mf) * 2 + k8) * 128 + lane * 4)) ^ akey];
                af[mf][0] = t.x; af[mf][1] = t.y; af[mf][2] = t.z; af[mf][3] = t.w;
            }
            #pragma unroll
            for (int mf = 0; mf < 4; mf++)
                #pragma unroll
                for (int nf = 0; nf < 4; nf++)
                    mma_tf32(acc[mf][nf], af[mf], (const uint32_t*)&bf[nf]);
        }
    };

    int nk = K >> 4;
    ldg_tile(0);
    sts_tile(0);
    if (nk > 1) ldg_tile(16);
    __syncthreads();

    for (int kt = 0; kt < nk; kt++) {
        int st = kt & 1;
        compute(kt, st);
        if (kt + 1 < nk) {
            sts_tile(st ^ 1);
            if (kt + 2 < nk) ldg_tile((kt + 2) * 16);
        }
        __syncthreads();
    }

    #pragma unroll
    for (int mf = 0; mf < 4; mf++) {
        int rbase = m0 + wm * 64 + mf * 16 + grp;
        #pragma unroll
        for (int half = 0; half < 2; half++) {
            int row = rbase + half * 8;
            if (row >= M) continue;
            #pragma unroll
            for (int nf = 0; nf < 4; nf++) {
                int col = wn * 32 + nf * 8 + q * 2;
                float v0 = acc[mf][nf][half * 2 + 0];
                float v1 = acc[mf][nf][half * 2 + 1];
                if (bias) { v0 += bias[col]; v1 += bias[col + 1]; }
                if (ACT == 1) { v0 = lrelu(v0); v1 = lrelu(v1); }
                else if (ACT == 2) { v0 = fmaxf(v0, 0.f); v1 = fmaxf(v1, 0.f); }
                long idx = (long)row * ldc + col;
                if (ACCUM) { C[idx] += v0; C[idx + 1] += v1; }
                else       { C[idx] = v0;  C[idx + 1] = v1; }
            }
        }
    }
}

// ---------------- L1: zero counters + prep all weights -----------------------
__global__ void k_L1(const float* __restrict__ des_w, const float* __restrict__ tweet_w,
                     const float* __restrict__ rel_w, const float* __restrict__ root_w,
                     const float* __restrict__ mlp_w1, float* __restrict__ bt) {
    int bid = blockIdx.x;
    if (bid < 391) {
        int i = bid * 256 + threadIdx.x;
        if (i < 2 * NN) g_cnt[i] = 0;
        if (i == 0) g_total = 0;
        return;
    }
    int pb = bid - 391;
    if (pb < 384)       dev_prep_b(des_w,   bt + BT_DES, 768, pb);
    else if (pb < 768)  dev_prep_b(tweet_w, bt + BT_TWE, 768, pb - 384);
    else if (pb < 1024) { int i = (pb - 768) >> 6;
                          dev_prep_b(rel_w + (size_t)i * 16384, bt + BT_REL + i * 16384, 128, (pb - 768) & 63); }
    else if (pb < 1152) { int l = (pb - 1024) >> 6;
                          dev_prep_b(root_w + (size_t)l * 16384, bt + BT_ROOT + l * 16384, 128, (pb - 1024) & 63); }
    else                dev_prep_b(mlp_w1, bt + BT_MLP1, 128, pb - 1152);
}

// ---------------- L2: des-GEMM ∥ tweets-GEMM ∥ hist ---------------------------
__global__ void __launch_bounds__(256, 2)
k_L2(const float* __restrict__ des, const float* __restrict__ tweets,
     const uint32_t* __restrict__ bt, const float* __restrict__ des_b,
     const float* __restrict__ tweet_b, float* __restrict__ ox,
     float* __restrict__ oh, const int* __restrict__ ei, const int* __restrict__ et) {
    __shared__ uint32_t As[2][2048];
    int bid = blockIdx.x;
    if (bid < 391)
        gemm_body<1, false>(des, bt + BT_DES, des_b, ox, NN, 768, 128, bid, As);
    else if (bid < 782)
        gemm_body<1, false>(tweets, bt + BT_TWE, tweet_b, oh, NN, 768, 128, bid - 391, As);
    else
        dev_hist(ei, et, bid - 782);
}

// ---------------- L3: combine (x = gx+gh+lrelu(num)+lrelu(cat)) ∥ assign -----
__global__ void k_L3(const float* __restrict__ numf, const float* __restrict__ catf,
                     const float* __restrict__ num_w, const float* __restrict__ num_b,
                     const float* __restrict__ cat_w, const float* __restrict__ cat_b,
                     const float* __restrict__ gx, const float* __restrict__ gh,
                     float* __restrict__ px) {
    int bid = blockIdx.x;
    if (bid >= 6250) { dev_assign(bid - 6250); return; }
    int wid  = threadIdx.x >> 5;
    int lane = threadIdx.x & 31;
    int row  = bid * 8 + wid;
    if (row >= NN) return;

    float nv[5], cv[6];
    #pragma unroll
    for (int k = 0; k < 5; k++) nv[k] = numf[row * 5 + k];
    #pragma unroll
    for (int k = 0; k < 6; k++) cv[k] = catf[row * 6 + k];

    float4 a = *(const float4*)&gx[(size_t)row * 128 + lane * 4];
    float4 b = *(const float4*)&gh[(size_t)row * 128 + lane * 4];
    const float* af = (const float*)&a;
    const float* bf = (const float*)&b;

    float o[4];
    #pragma unroll
    for (int u = 0; u < 4; u++) {
        int col = lane * 4 + u;
        float s = num_b[col];
        #pragma unroll
        for (int k = 0; k < 5; k++) s = fmaf(nv[k], num_w[k * 128 + col], s);
        float t = cat_b[col];
        #pragma unroll
        for (int k = 0; k < 6; k++) t = fmaf(cv[k], cat_w[k * 128 + col], t);
        o[u] = af[u] + bf[u] + lrelu(s) + lrelu(t);
    }
    *(float4*)&px[(size_t)row * 128 + lane * 4] = make_float4(o[0], o[1], o[2], o[3]);
}

// ---------------- RGCN multi-B GEMM: A resident in smem, B gmem-direct -------
// dyn smem: A = 8 ktiles x 2048 words (64KB). No inner-loop syncs.
__global__ void __launch_bounds__(256, 2)
k_rgcn3(const float* __restrict__ px,
        const uint32_t* __restrict__ b0p, const uint32_t* __restrict__ b1p,
        const uint32_t* __restrict__ b2p,
        float* __restrict__ py, float* __restrict__ proot,
        const int* __restrict__ ei, const int* __restrict__ et) {
    extern __shared__ uint32_t Asm[];
    int bid = blockIdx.x;
    if (bid >= 391) { dev_fill(ei, et, bid - 391); return; }

    int tid  = threadIdx.x;
    int lane = tid & 31;
    int w    = tid >> 5;
    int wm   = w & 1;
    int wn   = w >> 1;
    int m0   = bid * 128;
    int grp  = lane >> 2;
    int q    = lane & 3;

    // ---- load A fully (8 ktiles), convert + frag-permute into smem
    #pragma unroll
    for (int kt = 0; kt < 8; kt++) {
        #pragma unroll
        for (int u = 0; u < 2; u++) {
            int unit = tid + u * 256;
            int row  = unit >> 2;
            int c4   = unit & 3;
            int ar   = m0 + row; if (ar >= NN) ar = NN - 1;
            uint4 ra = *(const uint4*)&px[(size_t)ar * 128 + kt * 16 + c4 * 4];
            int m16  = row >> 4;
            int rbit = (row >> 3) & 1;
            int r7   = row & 7;
            int k8   = c4 >> 1;
            int vv   = rbit + 2 * (c4 & 1);
            uint32_t key = (uint32_t)(((r7 >> 1) & 3) << 2);
            uint32_t b0  = (uint32_t)(kt * 2048 + (m16 * 2 + k8) * 128 + r7 * 16 + vv);
            const float* vf = (const float*)&ra;
            Asm[(b0 +  0) ^ key] = f2tf32(vf[0]);
            Asm[(b0 +  4) ^ key] = f2tf32(vf[1]);
            Asm[(b0 +  8) ^ key] = f2tf32(vf[2]);
            Asm[(b0 + 12) ^ key] = f2tf32(vf[3]);
        }
    }
    __syncthreads();

    const uint32_t* bsel[3] = { b0p, b1p, b2p };
    float*          csel[3] = { py, py + 128, proot };
    int             lsel[3] = { 256, 256, 128 };

    uint32_t akey = (uint32_t)(((lane >> 3) & 3) << 2);

    #pragma unroll
    for (int b = 0; b < 3; b++) {
        const uint32_t* Bp = bsel[b];
        float* C = csel[b];
        int ldc = lsel[b];

        float acc[4][4][4];
        #pragma unroll
        for (int i = 0; i < 4; i++)
            #pragma unroll
            for (int j = 0; j < 4; j++)
                #pragma unroll
                for (int v = 0; v < 4; v++) acc[i][j][v] = 0.f;

        #pragma unroll
        for (int kt = 0; kt < 8; kt++) {
            const uint32_t* bbase = Bp + (size_t)kt * 2048;
            #pragma unroll
            for (int k8 = 0; k8 < 2; k8++) {
                uint32_t af[4][4];
                uint2 bf[4];
                #pragma unroll
                for (int nf = 0; nf < 4; nf++)
                    bf[nf] = *(const uint2*)&bbase[((wn * 4 + nf) * 2 + k8) * 64 + lane * 2];
                #pragma unroll
                for (int mf = 0; mf < 4; mf++) {
                    uint4 t = *(const uint4*)&Asm[((uint32_t)(kt * 2048 + ((wm * 4 + mf) * 2 + k8) * 128 + lane * 4)) ^ akey];
                    af[mf][0] = t.x; af[mf][1] = t.y; af[mf][2] = t.z; af[mf][3] = t.w;
                }
                #pragma unroll
                for (int mf = 0; mf < 4; mf++)
                    #pragma unroll
                    for (int nf = 0; nf < 4; nf++)
                        mma_tf32(acc[mf][nf], af[mf], (const uint32_t*)&bf[nf]);
            }
        }

        #pragma unroll
        for (int mf = 0; mf < 4; mf++) {
            int rbase = m0 + wm * 64 + mf * 16 + grp;
            #pragma unroll
            for (int half = 0; half < 2; half++) {
                int row = rbase + half * 8;
                if (row >= NN) continue;
                #pragma unroll
                for (int nf = 0; nf < 4; nf++) {
                    int col = wn * 32 + nf * 8 + q * 2;
                    long idx = (long)row * ldc + col;
                    C[idx]     = acc[mf][nf][half * 2 + 0];
                    C[idx + 1] = acc[mf][nf][half * 2 + 1];
                }
            }
        }
    }
}

// ---------------- gather ------------------------------------------------------
__global__ void k_gather(const float* __restrict__ y, const float* __restrict__ root,
                         const float* __restrict__ bias, float* __restrict__ xout) {
    int gw = (blockIdx.x * blockDim.x + threadIdx.x) >> 5;
    int lane = threadIdx.x & 31;
    if (gw >= NN) return;

    int beg = g_off[gw], end = beg + g_len[gw];
    float4 a0 = make_float4(0.f, 0.f, 0.f, 0.f);
    float4 a1 = make_float4(0.f, 0.f, 0.f, 0.f);

    for (int j = beg; j < end; j++) {
        int p = __ldg(&g_list[j]);
        const float4 v = *(const float4*)(y + (size_t)(p >> 1) * 256 + (p & 1) * 128 + lane * 4);
        if (p & 1) { a1.x += v.x; a1.y += v.y; a1.z += v.z; a1.w += v.w; }
        else       { a0.x += v.x; a0.y += v.y; a0.z += v.z; a0.w += v.w; }
    }

    float i0 = g_inv[gw], i1 = g_inv[NN + gw];
    size_t base = (size_t)gw * 128 + lane * 4;
    float4 rt = *(const float4*)(root + base);
    float b0 = bias[lane * 4 + 0], b1 = bias[lane * 4 + 1];
    float b2 = bias[lane * 4 + 2], b3 = bias[lane * 4 + 3];

    float4 o;
    o.x = lrelu(rt.x + b0 + a0.x * i0 + a1.x * i1);
    o.y = lrelu(rt.y + b1 + a0.y * i0 + a1.y * i1);
    o.z = lrelu(rt.z + b2 + a0.z * i0 + a1.z * i1);
    o.w = lrelu(rt.w + b3 + a0.w * i0 + a1.w * i1);
    *(float4*)(xout + base) = o;
}

// ---------------- L8: MLP1 GEMM + fused 2-wide head ---------------------------
__global__ void __launch_bounds__(256, 2)
k_mlp_head(const float* __restrict__ A, const uint32_t* __restrict__ Bp,
           const float* __restrict__ b1, const float* __restrict__ w2,
           const float* __restrict__ b2, float* __restrict__ out) {
    __shared__ uint32_t As[2][2048];
    __shared__ float w2s[256];
    __shared__ float outs[128][2];

    int tid  = threadIdx.x;
    int lane = tid & 31;
    int w    = tid >> 5;
    int wm   = w & 1;
    int wn   = w >> 1;
    int m0   = blockIdx.x * 128;
    int grp  = lane >> 2;
    int q    = lane & 3;

    w2s[tid & 255] = w2[tid & 255];
    outs[tid >> 1][tid & 1] = 0.f;

    float acc[4][4][4];
    #pragma unroll
    for (int i = 0; i < 4; i++)
        #pragma unroll
        for (int j = 0; j < 4; j++)
            #pragma unroll
            for (int v = 0; v < 4; v++) acc[i][j][v] = 0.f;

    uint4 ra[2];
    const int K = 128;

    auto ldg_tile = [&](int kc) {
        #pragma unroll
        for (int u = 0; u < 2; u++) {
            int unit = tid + u * 256;
            int row  = unit >> 2;
            int c4   = unit & 3;
            int ar   = m0 + row; if (ar >= NN) ar = NN - 1;
            ra[u] = *(const uint4*)&A[(size_t)ar * K + kc + c4 * 4];
        }
    };
    auto sts_tile = [&](int st) {
        #pragma unroll
        for (int u = 0; u < 2; u++) {
            int unit = tid + u * 256;
            int row  = unit >> 2;
            int c4   = unit & 3;
            int m16  = row >> 4;
            int rbit = (row >> 3) & 1;
            int r7   = row & 7;
            int k8   = c4 >> 1;
            int vv   = rbit + 2 * (c4 & 1);
            uint32_t key = (uint32_t)(((r7 >> 1) & 3) << 2);
            uint32_t b0  = (uint32_t)((m16 * 2 + k8) * 128 + r7 * 16 + vv);
            const float* vf = (const float*)&ra[u];
            As[st][(b0 +  0) ^ key] = f2tf32(vf[0]);
            As[st][(b0 +  4) ^ key] = f2tf32(vf[1]);
            As[st][(b0 +  8) ^ key] = f2tf32(vf[2]);
            As[st][(b0 + 12) ^ key] = f2tf32(vf[3]);
        }
    };
    uint32_t akey = (uint32_t)(((lane >> 3) & 3) << 2);
    auto compute = [&](int kt, int st) {
        const uint32_t* bbase = Bp + (size_t)kt * 2048;
        #pragma unroll
        for (int k8 = 0; k8 < 2; k8++) {
            uint32_t af[4][4];
            uint2 bf[4];
            #pragma unroll
            for (int nf = 0; nf < 4; nf++)
                bf[nf] = *(const uint2*)&bbase[((wn * 4 + nf) * 2 + k8) * 64 + lane * 2];
            #pragma unroll
            for (int mf = 0; mf < 4; mf++) {
                uint4 t = *(const uint4*)&As[st][((uint32_t)(((wm * 4 + mf) * 2 + k8) * 128 + lane * 4)) ^ akey];
                af[mf][0] = t.x; af[mf][1] = t.y; af[mf][2] = t.z; af[mf][3] = t.w;
            }
            #pragma unroll
            for (int mf = 0; mf < 4; mf++)
                #pragma unroll
                for (int nf = 0; nf < 4; nf++)
                    mma_tf32(acc[mf][nf], af[mf], (const uint32_t*)&bf[nf]);
        }
    };

    int nk = K >> 4;   // 8
    ldg_tile(0);
    sts_tile(0);
    ldg_tile(16);
    __syncthreads();
    for (int kt = 0; kt < nk; kt++) {
        int st = kt & 1;
        compute(kt, st);
        if (kt + 1 < nk) {
            sts_tile(st ^ 1);
            if (kt + 2 < nk) ldg_tile((kt + 2) * 16);
        }
        __syncthreads();
    }

    // head: out[row] = relu(acc + b1) @ w2 + b2
    #pragma unroll
    for (int mf = 0; mf < 4; mf++) {
        #pragma unroll
        for (int half = 0; half < 2; half++) {
            int rl = wm * 64 + mf * 16 + grp + half * 8;
            float p0 = 0.f, p1 = 0.f;
            #pragma unroll
            for (int nf = 0; nf < 4; nf++) {
                #pragma unroll
                for (int v = 0; v < 2; v++) {
                    int col = wn * 32 + nf * 8 + q * 2 + v;
                    float h = fmaxf(acc[mf][nf][half * 2 + v] + b1[col], 0.f);
                    p0 = fmaf(h, w2s[col * 2 + 0], p0);
                    p1 = fmaf(h, w2s[col * 2 + 1], p1);
                }
            }
            p0 += __shfl_xor_sync(0xFFFFFFFFu, p0, 1);
            p0 += __shfl_xor_sync(0xFFFFFFFFu, p0, 2);
            p1 += __shfl_xor_sync(0xFFFFFFFFu, p1, 1);
            p1 += __shfl_xor_sync(0xFFFFFFFFu, p1, 2);
            if (q == 0) {
                atomicAdd(&outs[rl][0], p0);
                atomicAdd(&outs[rl][1], p1);
            }
        }
    }
    __syncthreads();
    int r = tid >> 1, c = tid & 1;
    int row = m0 + r;
    if (row < NN) out[row * 2 + c] = outs[r][c] + b2[c];
}

// ---------------- launch -------------------------------------------------------
#define RGCN_SMEM 65536

extern "C" void kernel_launch(void* const* d_in, const int* in_sizes, int n_in,
                              void* d_out, int out_size) {
    const float* des     = (const float*)d_in[0];
    const float* tweets  = (const float*)d_in[1];
    const float* numf    = (const float*)d_in[2];
    const float* catf    = (const float*)d_in[3];
    const int*   ei      = (const int*)d_in[4];
    const int*   et      = (const int*)d_in[5];
    const float* des_w   = (const float*)d_in[6];
    const float* des_b   = (const float*)d_in[7];
    const float* tweet_w = (const float*)d_in[8];
    const float* tweet_b = (const float*)d_in[9];
    const float* num_w   = (const float*)d_in[10];
    const float* num_b   = (const float*)d_in[11];
    const float* cat_w   = (const float*)d_in[12];
    const float* cat_b   = (const float*)d_in[13];
    const float* rel_w   = (const float*)d_in[14];
    const float* root_w  = (const float*)d_in[15];
    const float* rgcn_b  = (const float*)d_in[16];
    const float* mlp_w1  = (const float*)d_in[17];
    const float* mlp_b1  = (const float*)d_in[18];
    const float* mlp_w2  = (const float*)d_in[19];
    const float* mlp_b2  = (const float*)d_in[20];
    float* out = (float*)d_out;

    float *px, *ph, *py, *proot, *pbt;
    cudaGetSymbolAddress((void**)&px,    g_x);
    cudaGetSymbolAddress((void**)&ph,    g_h);
    cudaGetSymbolAddress((void**)&py,    g_y);
    cudaGetSymbolAddress((void**)&proot, g_root);
    cudaGetSymbolAddress((void**)&pbt,   g_bt);
    const uint32_t* ubt = (const uint32_t*)pbt;

    cudaFuncSetAttribute(k_rgcn3, cudaFuncAttributeMaxDynamicSharedMemorySize, RGCN_SMEM);

    // L1: zero counters ∥ prep all weights
    k_L1<<<391 + 1216, 256>>>(des_w, tweet_w, rel_w, root_w, mlp_w1, pbt);

    // L2: des-GEMM ∥ tweets-GEMM ∥ hist
    k_L2<<<782 + 6250, 256>>>(des, tweets, ubt, des_b, tweet_b, px, ph, ei, et);

    // L3: combine ∥ assign
    k_L3<<<6250 + 196, 256>>>(numf, catf, num_w, num_b, cat_w, cat_b, px, ph, px);

    // L4: RGCN layer 0 (A-resident 3-GEMM, B direct) ∥ fill
    k_rgcn3<<<391 + 6250, 256, RGCN_SMEM>>>(px, ubt + BT_REL, ubt + BT_REL + 16384,
                                            ubt + BT_ROOT, py, proot, ei, et);
    k_gather<<<(NN * 32) / 256, 256>>>(py, proot, rgcn_b, px);

    // L6: RGCN layer 1
    k_rgcn3<<<391, 256, RGCN_SMEM>>>(px, ubt + BT_REL + 2 * 16384, ubt + BT_REL + 3 * 16384,
                                     ubt + BT_ROOT + 16384, py, proot, ei, et);
    k_gather<<<(NN * 32) / 256, 256>>>(py, proot, rgcn_b + 128, px);

    // L8: MLP1 + fused head
    k_mlp_head<<<391, 256>>>(px, ubt + BT_MLP1, mlp_b1, mlp_w2, mlp_b2, out);
}

// round 8
// speedup vs baseline: 3.7658x; 1.0664x over previous
#include <cuda_runtime.h>
#include <cuda_bf16.h>
#include <cuda_fp16.h>
#include <cstdint>

#define NN 50000
#define EE 1600000

// ---------------- scratch (device globals) ----------------------------------
__device__ float g_x[NN * 128];      // node features (px)
__device__ float g_h[NN * 128];      // tweets projection
__device__ __half g_y[NN * 256];     // [Y0 | Y1] per node, fp16 messages
__device__ float g_root[NN * 128];
__device__ float g_bt[311296];       // pre-permuted tf32 weights
__device__ int   g_cnt[2 * NN];
__device__ int   g_off[NN];
__device__ int   g_len[NN];
__device__ int   g_cur[NN];
__device__ int   g_list[EE];
__device__ float g_inv[2 * NN];
__device__ int   g_total;

#define BT_DES  0
#define BT_TWE  98304
#define BT_REL  196608
#define BT_ROOT 262144
#define BT_MLP1 294912

__device__ __forceinline__ float lrelu(float v) { return v > 0.f ? v : 0.01f * v; }

__device__ __forceinline__ uint32_t f2tf32(float x) {
    uint32_t r;
    asm("cvt.rna.tf32.f32 %0, %1;" : "=r"(r) : "f"(x));
    return r;
}

__device__ __forceinline__ void mma_tf32(float c[4], const uint32_t a[4], const uint32_t b[2]) {
    asm volatile("mma.sync.aligned.m16n8k8.row.col.f32.tf32.tf32.f32 "
        "{%0,%1,%2,%3}, {%4,%5,%6,%7}, {%8,%9}, {%0,%1,%2,%3};"
        : "+f"(c[0]), "+f"(c[1]), "+f"(c[2]), "+f"(c[3])
        : "r"(a[0]), "r"(a[1]), "r"(a[2]), "r"(a[3]), "r"(b[0]), "r"(b[1]));
}

// ---------------- device helpers ---------------------------------------------
__device__ __forceinline__ void dev_prep_b(const float* __restrict__ src,
                                           float* __restrict__ dst, int K, int blk) {
    int idx = blk * 256 + threadIdx.x;
    if (idx >= K * 128) return;
    int w  = idx & 2047;
    int n8 = w >> 7;
    int k8 = (w >> 6) & 1;
    int tw = (w & 63) >> 1;
    int vb = w & 1;
    int n  = n8 * 8 + (tw >> 2);
    int kk = k8 * 8 + vb * 4 + (tw & 3);
    int k  = (idx >> 11) * 16 + kk;
    dst[idx] = __uint_as_float(f2tf32(src[(size_t)k * 128 + n]));
}

__device__ __forceinline__ void dev_hist(const int* __restrict__ ei,
                                         const int* __restrict__ et, int blk) {
    int e = blk * 256 + threadIdx.x;
    if (e < EE) atomicAdd(&g_cnt[et[e] * NN + ei[EE + e]], 1);
}

__device__ __forceinline__ void dev_assign(int blk) {
    int i = blk * 256 + threadIdx.x;
    if (i >= NN) return;
    int c0 = g_cnt[i], c1 = g_cnt[NN + i];
    int deg = c0 + c1;
    int pos = atomicAdd(&g_total, deg);
    g_off[i] = pos;
    g_cur[i] = pos;
    g_len[i] = deg;
    g_inv[i]      = 1.0f / (c0 > 0 ? (float)c0 : 1.0f);
    g_inv[NN + i] = 1.0f / (c1 > 0 ? (float)c1 : 1.0f);
}

__device__ __forceinline__ void dev_fill(const int* __restrict__ ei,
                                         const int* __restrict__ et, int blk) {
    int e = blk * 256 + threadIdx.x;
    if (e < EE) {
        int pos = atomicAdd(&g_cur[ei[EE + e]], 1);
        g_list[pos] = (ei[e] << 1) | et[e];
    }
}

// ---------------- GEMM body (tf32 mma.sync, A smem-staged, B gmem-direct) ----
template <int ACT, bool ACCUM>
__device__ __forceinline__ void gemm_body(
    const float* __restrict__ A, const uint32_t* __restrict__ Bp,
    const float* __restrict__ bias, float* __restrict__ C,
    int M, int K, int ldc, int bidx,
    uint32_t (*As)[2048]) {

    int tid  = threadIdx.x;
    int lane = tid & 31;
    int w    = tid >> 5;
    int wm   = w & 1;
    int wn   = w >> 1;
    int m0   = bidx * 128;
    int grp  = lane >> 2;
    int q    = lane & 3;

    float acc[4][4][4];
    #pragma unroll
    for (int i = 0; i < 4; i++)
        #pragma unroll
        for (int j = 0; j < 4; j++)
            #pragma unroll
            for (int v = 0; v < 4; v++) acc[i][j][v] = 0.f;

    uint4 ra[2];

    auto ldg_tile = [&](int kc) {
        #pragma unroll
        for (int u = 0; u < 2; u++) {
            int unit = tid + u * 256;
            int row  = unit >> 2;
            int c4   = unit & 3;
            int ar   = m0 + row; if (ar >= M) ar = M - 1;
            ra[u] = *(const uint4*)&A[(size_t)ar * K + kc + c4 * 4];
        }
    };

    auto sts_tile = [&](int st) {
        #pragma unroll
        for (int u = 0; u < 2; u++) {
            int unit = tid + u * 256;
            int row  = unit >> 2;
            int c4   = unit & 3;
            int m16  = row >> 4;
            int rbit = (row >> 3) & 1;
            int r7   = row & 7;
            int k8   = c4 >> 1;
            int vv   = rbit + 2 * (c4 & 1);
            uint32_t key = (uint32_t)(((r7 >> 1) & 3) << 2);
            uint32_t b0  = (uint32_t)((m16 * 2 + k8) * 128 + r7 * 16 + vv);
            const float* vf = (const float*)&ra[u];
            As[st][(b0 +  0) ^ key] = f2tf32(vf[0]);
            As[st][(b0 +  4) ^ key] = f2tf32(vf[1]);
            As[st][(b0 +  8) ^ key] = f2tf32(vf[2]);
            As[st][(b0 + 12) ^ key] = f2tf32(vf[3]);
        }
    };

    uint32_t akey = (uint32_t)(((lane >> 3) & 3) << 2);

    auto compute = [&](int kt, int st) {
        const uint32_t* bbase = Bp + (size_t)kt * 2048;
        #pragma unroll
        for (int k8 = 0; k8 < 2; k8++) {
            uint32_t af[4][4];
            uint2 bf[4];
            #pragma unroll
            for (int nf = 0; nf < 4; nf++)
                bf[nf] = *(const uint2*)&bbase[((wn * 4 + nf) * 2 + k8) * 64 + lane * 2];
            #pragma unroll
            for (int mf = 0; mf < 4; mf++) {
                uint4 t = *(const uint4*)&As[st][((uint32_t)(((wm * 4 + mf) * 2 + k8) * 128 + lane * 4)) ^ akey];
                af[mf][0] = t.x; af[mf][1] = t.y; af[mf][2] = t.z; af[mf][3] = t.w;
            }
            #pragma unroll
            for (int mf = 0; mf < 4; mf++)
                #pragma unroll
                for (int nf = 0; nf < 4; nf++)
                    mma_tf32(acc[mf][nf], af[mf], (const uint32_t*)&bf[nf]);
        }
    };

    int nk = K >> 4;
    ldg_tile(0);
    sts_tile(0);
    if (nk > 1) ldg_tile(16);
    __syncthreads();

    for (int kt = 0; kt < nk; kt++) {
        int st = kt & 1;
        compute(kt, st);
        if (kt + 1 < nk) {
            sts_tile(st ^ 1);
            if (kt + 2 < nk) ldg_tile((kt + 2) * 16);
        }
        __syncthreads();
    }

    #pragma unroll
    for (int mf = 0; mf < 4; mf++) {
        int rbase = m0 + wm * 64 + mf * 16 + grp;
        #pragma unroll
        for (int half = 0; half < 2; half++) {
            int row = rbase + half * 8;
            if (row >= M) continue;
            #pragma unroll
            for (int nf = 0; nf < 4; nf++) {
                int col = wn * 32 + nf * 8 + q * 2;
                float v0 = acc[mf][nf][half * 2 + 0];
                float v1 = acc[mf][nf][half * 2 + 1];
                if (bias) { v0 += bias[col]; v1 += bias[col + 1]; }
                if (ACT == 1) { v0 = lrelu(v0); v1 = lrelu(v1); }
                else if (ACT == 2) { v0 = fmaxf(v0, 0.f); v1 = fmaxf(v1, 0.f); }
                long idx = (long)row * ldc + col;
                if (ACCUM) { C[idx] += v0; C[idx + 1] += v1; }
                else       { C[idx] = v0;  C[idx + 1] = v1; }
            }
        }
    }
}

// ---------------- L1: zero counters + prep all weights -----------------------
__global__ void k_L1(const float* __restrict__ des_w, const float* __restrict__ tweet_w,
                     const float* __restrict__ rel_w, const float* __restrict__ root_w,
                     const float* __restrict__ mlp_w1, float* __restrict__ bt) {
    int bid = blockIdx.x;
    if (bid < 391) {
        int i = bid * 256 + threadIdx.x;
        if (i < 2 * NN) g_cnt[i] = 0;
        if (i == 0) g_total = 0;
        return;
    }
    int pb = bid - 391;
    if (pb < 384)       dev_prep_b(des_w,   bt + BT_DES, 768, pb);
    else if (pb < 768)  dev_prep_b(tweet_w, bt + BT_TWE, 768, pb - 384);
    else if (pb < 1024) { int i = (pb - 768) >> 6;
                          dev_prep_b(rel_w + (size_t)i * 16384, bt + BT_REL + i * 16384, 128, (pb - 768) & 63); }
    else if (pb < 1152) { int l = (pb - 1024) >> 6;
                          dev_prep_b(root_w + (size_t)l * 16384, bt + BT_ROOT + l * 16384, 128, (pb - 1024) & 63); }
    else                dev_prep_b(mlp_w1, bt + BT_MLP1, 128, pb - 1152);
}

// ---------------- L2: des-GEMM ∥ tweets-GEMM ∥ hist ---------------------------
__global__ void __launch_bounds__(256, 2)
k_L2(const float* __restrict__ des, const float* __restrict__ tweets,
     const uint32_t* __restrict__ bt, const float* __restrict__ des_b,
     const float* __restrict__ tweet_b, float* __restrict__ ox,
     float* __restrict__ oh, const int* __restrict__ ei, const int* __restrict__ et) {
    __shared__ uint32_t As[2][2048];
    int bid = blockIdx.x;
    if (bid < 391)
        gemm_body<1, false>(des, bt + BT_DES, des_b, ox, NN, 768, 128, bid, As);
    else if (bid < 782)
        gemm_body<1, false>(tweets, bt + BT_TWE, tweet_b, oh, NN, 768, 128, bid - 391, As);
    else
        dev_hist(ei, et, bid - 782);
}

// ---------------- L3: combine (x = gx+gh+lrelu(num)+lrelu(cat)) ∥ assign -----
__global__ void k_L3(const float* __restrict__ numf, const float* __restrict__ catf,
                     const float* __restrict__ num_w, const float* __restrict__ num_b,
                     const float* __restrict__ cat_w, const float* __restrict__ cat_b,
                     const float* __restrict__ gx, const float* __restrict__ gh,
                     float* __restrict__ px) {
    int bid = blockIdx.x;
    if (bid >= 6250) { dev_assign(bid - 6250); return; }
    int wid  = threadIdx.x >> 5;
    int lane = threadIdx.x & 31;
    int row  = bid * 8 + wid;
    if (row >= NN) return;

    float nv[5], cv[6];
    #pragma unroll
    for (int k = 0; k < 5; k++) nv[k] = numf[row * 5 + k];
    #pragma unroll
    for (int k = 0; k < 6; k++) cv[k] = catf[row * 6 + k];

    float4 a = *(const float4*)&gx[(size_t)row * 128 + lane * 4];
    float4 b = *(const float4*)&gh[(size_t)row * 128 + lane * 4];
    const float* af = (const float*)&a;
    const float* bf = (const float*)&b;

    float o[4];
    #pragma unroll
    for (int u = 0; u < 4; u++) {
        int col = lane * 4 + u;
        float s = num_b[col];
        #pragma unroll
        for (int k = 0; k < 5; k++) s = fmaf(nv[k], num_w[k * 128 + col], s);
        float t = cat_b[col];
        #pragma unroll
        for (int k = 0; k < 6; k++) t = fmaf(cv[k], cat_w[k * 128 + col], t);
        o[u] = af[u] + bf[u] + lrelu(s) + lrelu(t);
    }
    *(float4*)&px[(size_t)row * 128 + lane * 4] = make_float4(o[0], o[1], o[2], o[3]);
}

// ---------------- RGCN multi-B GEMM: A resident, B gmem-direct, fp16 y out ---
__global__ void __launch_bounds__(256, 2)
k_rgcn3(const float* __restrict__ px,
        const uint32_t* __restrict__ b0p, const uint32_t* __restrict__ b1p,
        const uint32_t* __restrict__ b2p,
        __half* __restrict__ py, float* __restrict__ proot,
        const int* __restrict__ ei, const int* __restrict__ et) {
    extern __shared__ uint32_t Asm[];
    int bid = blockIdx.x;
    if (bid >= 391) { dev_fill(ei, et, bid - 391); return; }

    int tid  = threadIdx.x;
    int lane = tid & 31;
    int w    = tid >> 5;
    int wm   = w & 1;
    int wn   = w >> 1;
    int m0   = bid * 128;
    int grp  = lane >> 2;
    int q    = lane & 3;

    // ---- load A fully (8 ktiles), convert + frag-permute into smem
    #pragma unroll
    for (int kt = 0; kt < 8; kt++) {
        #pragma unroll
        for (int u = 0; u < 2; u++) {
            int unit = tid + u * 256;
            int row  = unit >> 2;
            int c4   = unit & 3;
            int ar   = m0 + row; if (ar >= NN) ar = NN - 1;
            uint4 ra = *(const uint4*)&px[(size_t)ar * 128 + kt * 16 + c4 * 4];
            int m16  = row >> 4;
            int rbit = (row >> 3) & 1;
            int r7   = row & 7;
            int k8   = c4 >> 1;
            int vv   = rbit + 2 * (c4 & 1);
            uint32_t key = (uint32_t)(((r7 >> 1) & 3) << 2);
            uint32_t b0  = (uint32_t)(kt * 2048 + (m16 * 2 + k8) * 128 + r7 * 16 + vv);
            const float* vf = (const float*)&ra;
            Asm[(b0 +  0) ^ key] = f2tf32(vf[0]);
            Asm[(b0 +  4) ^ key] = f2tf32(vf[1]);
            Asm[(b0 +  8) ^ key] = f2tf32(vf[2]);
            Asm[(b0 + 12) ^ key] = f2tf32(vf[3]);
        }
    }
    __syncthreads();

    const uint32_t* bsel[3] = { b0p, b1p, b2p };
    uint32_t akey = (uint32_t)(((lane >> 3) & 3) << 2);

    #pragma unroll
    for (int b = 0; b < 3; b++) {
        const uint32_t* Bp = bsel[b];

        float acc[4][4][4];
        #pragma unroll
        for (int i = 0; i < 4; i++)
            #pragma unroll
            for (int j = 0; j < 4; j++)
                #pragma unroll
                for (int v = 0; v < 4; v++) acc[i][j][v] = 0.f;

        #pragma unroll
        for (int kt = 0; kt < 8; kt++) {
            const uint32_t* bbase = Bp + (size_t)kt * 2048;
            #pragma unroll
            for (int k8 = 0; k8 < 2; k8++) {
                uint32_t af[4][4];
                uint2 bf[4];
                #pragma unroll
                for (int nf = 0; nf < 4; nf++)
                    bf[nf] = *(const uint2*)&bbase[((wn * 4 + nf) * 2 + k8) * 64 + lane * 2];
                #pragma unroll
                for (int mf = 0; mf < 4; mf++) {
                    uint4 t = *(const uint4*)&Asm[((uint32_t)(kt * 2048 + ((wm * 4 + mf) * 2 + k8) * 128 + lane * 4)) ^ akey];
                    af[mf][0] = t.x; af[mf][1] = t.y; af[mf][2] = t.z; af[mf][3] = t.w;
                }
                #pragma unroll
                for (int mf = 0; mf < 4; mf++)
                    #pragma unroll
                    for (int nf = 0; nf < 4; nf++)
                        mma_tf32(acc[mf][nf], af[mf], (const uint32_t*)&bf[nf]);
            }
        }

        #pragma unroll
        for (int mf = 0; mf < 4; mf++) {
            int rbase = m0 + wm * 64 + mf * 16 + grp;
            #pragma unroll
            for (int half = 0; half < 2; half++) {
                int row = rbase + half * 8;
                if (row >= NN) continue;
                #pragma unroll
                for (int nf = 0; nf < 4; nf++) {
                    int col = wn * 32 + nf * 8 + q * 2;
                    float v0 = acc[mf][nf][half * 2 + 0];
                    float v1 = acc[mf][nf][half * 2 + 1];
                    if (b == 2) {
                        long idx = (long)row * 128 + col;
                        proot[idx]     = v0;
                        proot[idx + 1] = v1;
                    } else {
                        __half2 hv = __floats2half2_rn(v0, v1);
                        *(__half2*)&py[(size_t)row * 256 + b * 128 + col] = hv;
                    }
                }
            }
        }
    }
}

// ---------------- gather (fp16 messages, fp32 accumulate) --------------------
__global__ void k_gather(const __half* __restrict__ y, const float* __restrict__ root,
                         const float* __restrict__ bias, float* __restrict__ xout) {
    int gw = (blockIdx.x * blockDim.x + threadIdx.x) >> 5;
    int lane = threadIdx.x & 31;
    if (gw >= NN) return;

    int beg = g_off[gw], end = beg + g_len[gw];
    float a0[4] = {0.f, 0.f, 0.f, 0.f};
    float a1[4] = {0.f, 0.f, 0.f, 0.f};

    for (int j = beg; j < end; j++) {
        int p = __ldg(&g_list[j]);
        const uint2 raw = *(const uint2*)(y + (size_t)(p >> 1) * 256 + (p & 1) * 128 + lane * 4);
        float2 f01 = __half22float2(*(const __half2*)&raw.x);
        float2 f23 = __half22float2(*(const __half2*)&raw.y);
        if (p & 1) { a1[0] += f01.x; a1[1] += f01.y; a1[2] += f23.x; a1[3] += f23.y; }
        else       { a0[0] += f01.x; a0[1] += f01.y; a0[2] += f23.x; a0[3] += f23.y; }
    }

    float i0 = g_inv[gw], i1 = g_inv[NN + gw];
    size_t base = (size_t)gw * 128 + lane * 4;
    float4 rt = *(const float4*)(root + base);
    float b0 = bias[lane * 4 + 0], b1 = bias[lane * 4 + 1];
    float b2 = bias[lane * 4 + 2], b3 = bias[lane * 4 + 3];

    float4 o;
    o.x = lrelu(rt.x + b0 + a0[0] * i0 + a1[0] * i1);
    o.y = lrelu(rt.y + b1 + a0[1] * i0 + a1[1] * i1);
    o.z = lrelu(rt.z + b2 + a0[2] * i0 + a1[2] * i1);
    o.w = lrelu(rt.w + b3 + a0[3] * i0 + a1[3] * i1);
    *(float4*)(xout + base) = o;
}

// ---------------- L8: MLP1 GEMM + fused 2-wide head ---------------------------
__global__ void __launch_bounds__(256, 2)
k_mlp_head(const float* __restrict__ A, const uint32_t* __restrict__ Bp,
           const float* __restrict__ b1, const float* __restrict__ w2,
           const float* __restrict__ b2, float* __restrict__ out) {
    __shared__ uint32_t As[2][2048];
    __shared__ float w2s[256];
    __shared__ float outs[128][2];

    int tid  = threadIdx.x;
    int lane = tid & 31;
    int w    = tid >> 5;
    int wm   = w & 1;
    int wn   = w >> 1;
    int m0   = blockIdx.x * 128;
    int grp  = lane >> 2;
    int q    = lane & 3;

    w2s[tid & 255] = w2[tid & 255];
    outs[tid >> 1][tid & 1] = 0.f;

    float acc[4][4][4];
    #pragma unroll
    for (int i = 0; i < 4; i++)
        #pragma unroll
        for (int j = 0; j < 4; j++)
            #pragma unroll
            for (int v = 0; v < 4; v++) acc[i][j][v] = 0.f;

    uint4 ra[2];
    const int K = 128;

    auto ldg_tile = [&](int kc) {
        #pragma unroll
        for (int u = 0; u < 2; u++) {
            int unit = tid + u * 256;
            int row  = unit >> 2;
            int c4   = unit & 3;
            int ar   = m0 + row; if (ar >= NN) ar = NN - 1;
            ra[u] = *(const uint4*)&A[(size_t)ar * K + kc + c4 * 4];
        }
    };
    auto sts_tile = [&](int st) {
        #pragma unroll
        for (int u = 0; u < 2; u++) {
            int unit = tid + u * 256;
            int row  = unit >> 2;
            int c4   = unit & 3;
            int m16  = row >> 4;
            int rbit = (row >> 3) & 1;
            int r7   = row & 7;
            int k8   = c4 >> 1;
            int vv   = rbit + 2 * (c4 & 1);
            uint32_t key = (uint32_t)(((r7 >> 1) & 3) << 2);
            uint32_t b0  = (uint32_t)((m16 * 2 + k8) * 128 + r7 * 16 + vv);
            const float* vf = (const float*)&ra[u];
            As[st][(b0 +  0) ^ key] = f2tf32(vf[0]);
            As[st][(b0 +  4) ^ key] = f2tf32(vf[1]);
            As[st][(b0 +  8) ^ key] = f2tf32(vf[2]);
            As[st][(b0 + 12) ^ key] = f2tf32(vf[3]);
        }
    };
    uint32_t akey = (uint32_t)(((lane >> 3) & 3) << 2);
    auto compute = [&](int kt, int st) {
        const uint32_t* bbase = Bp + (size_t)kt * 2048;
        #pragma unroll
        for (int k8 = 0; k8 < 2; k8++) {
            uint32_t af[4][4];
            uint2 bf[4];
            #pragma unroll
            for (int nf = 0; nf < 4; nf++)
                bf[nf] = *(const uint2*)&bbase[((wn * 4 + nf) * 2 + k8) * 64 + lane * 2];
            #pragma unroll
            for (int mf = 0; mf < 4; mf++) {
                uint4 t = *(const uint4*)&As[st][((uint32_t)(((wm * 4 + mf) * 2 + k8) * 128 + lane * 4)) ^ akey];
                af[mf][0] = t.x; af[mf][1] = t.y; af[mf][2] = t.z; af[mf][3] = t.w;
            }
            #pragma unroll
            for (int mf = 0; mf < 4; mf++)
                #pragma unroll
                for (int nf = 0; nf < 4; nf++)
                    mma_tf32(acc[mf][nf], af[mf], (const uint32_t*)&bf[nf]);
        }
    };

    int nk = K >> 4;   // 8
    ldg_tile(0);
    sts_tile(0);
    ldg_tile(16);
    __syncthreads();
    for (int kt = 0; kt < nk; kt++) {
        int st = kt & 1;
        compute(kt, st);
        if (kt + 1 < nk) {
            sts_tile(st ^ 1);
            if (kt + 2 < nk) ldg_tile((kt + 2) * 16);
        }
        __syncthreads();
    }

    // head: out[row] = relu(acc + b1) @ w2 + b2
    #pragma unroll
    for (int mf = 0; mf < 4; mf++) {
        #pragma unroll
        for (int half = 0; half < 2; half++) {
            int rl = wm * 64 + mf * 16 + grp + half * 8;
            float p0 = 0.f, p1 = 0.f;
            #pragma unroll
            for (int nf = 0; nf < 4; nf++) {
                #pragma unroll
                for (int v = 0; v < 2; v++) {
                    int col = wn * 32 + nf * 8 + q * 2 + v;
                    float h = fmaxf(acc[mf][nf][half * 2 + v] + b1[col], 0.f);
                    p0 = fmaf(h, w2s[col * 2 + 0], p0);
                    p1 = fmaf(h, w2s[col * 2 + 1], p1);
                }
            }
            p0 += __shfl_xor_sync(0xFFFFFFFFu, p0, 1);
            p0 += __shfl_xor_sync(0xFFFFFFFFu, p0, 2);
            p1 += __shfl_xor_sync(0xFFFFFFFFu, p1, 1);
            p1 += __shfl_xor_sync(0xFFFFFFFFu, p1, 2);
            if (q == 0) {
                atomicAdd(&outs[rl][0], p0);
                atomicAdd(&outs[rl][1], p1);
            }
        }
    }
    __syncthreads();
    int r = tid >> 1, c = tid & 1;
    int row = m0 + r;
    if (row < NN) out[row * 2 + c] = outs[r][c] + b2[c];
}

// ---------------- launch -------------------------------------------------------
#define RGCN_SMEM 65536

extern "C" void kernel_launch(void* const* d_in, const int* in_sizes, int n_in,
                              void* d_out, int out_size) {
    const float* des     = (const float*)d_in[0];
    const float* tweets  = (const float*)d_in[1];
    const float* numf    = (const float*)d_in[2];
    const float* catf    = (const float*)d_in[3];
    const int*   ei      = (const int*)d_in[4];
    const int*   et      = (const int*)d_in[5];
    const float* des_w   = (const float*)d_in[6];
    const float* des_b   = (const float*)d_in[7];
    const float* tweet_w = (const float*)d_in[8];
    const float* tweet_b = (const float*)d_in[9];
    const float* num_w   = (const float*)d_in[10];
    const float* num_b   = (const float*)d_in[11];
    const float* cat_w   = (const float*)d_in[12];
    const float* cat_b   = (const float*)d_in[13];
    const float* rel_w   = (const float*)d_in[14];
    const float* root_w  = (const float*)d_in[15];
    const float* rgcn_b  = (const float*)d_in[16];
    const float* mlp_w1  = (const float*)d_in[17];
    const float* mlp_b1  = (const float*)d_in[18];
    const float* mlp_w2  = (const float*)d_in[19];
    const float* mlp_b2  = (const float*)d_in[20];
    float* out = (float*)d_out;

    float *px, *ph, *proot, *pbt;
    __half *py;
    cudaGetSymbolAddress((void**)&px,    g_x);
    cudaGetSymbolAddress((void**)&ph,    g_h);
    cudaGetSymbolAddress((void**)&py,    g_y);
    cudaGetSymbolAddress((void**)&proot, g_root);
    cudaGetSymbolAddress((void**)&pbt,   g_bt);
    const uint32_t* ubt = (const uint32_t*)pbt;

    cudaFuncSetAttribute(k_rgcn3, cudaFuncAttributeMaxDynamicSharedMemorySize, RGCN_SMEM);

    // L1: zero counters ∥ prep all weights
    k_L1<<<391 + 1216, 256>>>(des_w, tweet_w, rel_w, root_w, mlp_w1, pbt);

    // L2: des-GEMM ∥ tweets-GEMM ∥ hist
    k_L2<<<782 + 6250, 256>>>(des, tweets, ubt, des_b, tweet_b, px, ph, ei, et);

    // L3: combine ∥ assign
    k_L3<<<6250 + 196, 256>>>(numf, catf, num_w, num_b, cat_w, cat_b, px, ph, px);

    // L4: RGCN layer 0 (A-resident 3-GEMM, fp16 y) ∥ fill
    k_rgcn3<<<391 + 6250, 256, RGCN_SMEM>>>(px, ubt + BT_REL, ubt + BT_REL + 16384,
                                            ubt + BT_ROOT, py, proot, ei, et);
    k_gather<<<(NN * 32) / 256, 256>>>(py, proot, rgcn_b, px);

    // L6: RGCN layer 1
    k_rgcn3<<<391, 256, RGCN_SMEM>>>(px, ubt + BT_REL + 2 * 16384, ubt + BT_REL + 3 * 16384,
                                     ubt + BT_ROOT + 16384, py, proot, ei, et);
    k_gather<<<(NN * 32) / 256, 256>>>(py, proot, rgcn_b + 128, px);

    // L8: MLP1 + fused head
    k_mlp_head<<<391, 256>>>(px, ubt + BT_MLP1, mlp_b1, mlp_w2, mlp_b2, out);
}